// round 2
// baseline (speedup 1.0000x reference)
#include <cuda_runtime.h>

#define BB   4
#define SS   2048
#define DD   1024
#define DQKC 128
#define DVC  256
#define MM   (BB * SS)   // 8192

typedef unsigned long long u64;

// Scratch (device globals — no allocation allowed)
__device__ float g_Q[MM * DQKC];
__device__ float g_K[MM * DQKC];
__device__ float g_V[MM * DVC];
__device__ float g_G[MM * DVC];
__device__ float g_AV[MM * DVC];
__device__ float g_Q2[MM];
__device__ float g_K2[MM];

// ---- packed fp32x2 helpers (Blackwell FFMA2) --------------------------------
__device__ __forceinline__ u64 pk2(float lo, float hi) {
    u64 r; asm("mov.b64 %0, {%1, %2};" : "=l"(r) : "f"(lo), "f"(hi)); return r;
}
__device__ __forceinline__ void upk2(float& lo, float& hi, u64 p) {
    asm("mov.b64 {%0, %1}, %2;" : "=f"(lo), "=f"(hi) : "l"(p));
}
__device__ __forceinline__ void ffma2(u64& d, u64 a, u64 b) {
    asm("fma.rn.f32x2 %0, %1, %2, %0;" : "+l"(d) : "l"(a), "l"(b));
}

// ---------------------------------------------------------------------------
// Kernel 1: fused QKVG projections.  Y = X @ W + b
// BM=128, BN=128, BK=16, 256 threads, 8x8 microtile (f32x2 packed).
// ---------------------------------------------------------------------------
__global__ __launch_bounds__(256) void proj_kernel(
    const float* __restrict__ X,
    const float* __restrict__ Wq, const float* __restrict__ bq,
    const float* __restrict__ Wk, const float* __restrict__ bk,
    const float* __restrict__ Wv, const float* __restrict__ bv,
    const float* __restrict__ Wg, const float* __restrict__ bg)
{
    __shared__ float Xs[16][132];   // transposed: Xs[k][m]
    __shared__ float Ws[16][132];   // Ws[k][n]

    const float* W; const float* bias; float* out; int N; int n0;
    switch (blockIdx.y) {
        case 0:  W = Wq; bias = bq; out = g_Q; N = DQKC; n0 = 0;   break;
        case 1:  W = Wk; bias = bk; out = g_K; N = DQKC; n0 = 0;   break;
        case 2:  W = Wv; bias = bv; out = g_V; N = DVC;  n0 = 0;   break;
        case 3:  W = Wv; bias = bv; out = g_V; N = DVC;  n0 = 128; break;
        case 4:  W = Wg; bias = bg; out = g_G; N = DVC;  n0 = 0;   break;
        default: W = Wg; bias = bg; out = g_G; N = DVC;  n0 = 128; break;
    }
    const int m0  = blockIdx.x * 128;
    const int tid = threadIdx.x;
    const int tx  = tid & 15;
    const int ty  = tid >> 4;

    const int lm = tid >> 2;
    const int lk = (tid & 3) * 4;
    const int wr = tid >> 5;
    const int wc = (tid & 31) * 4;

    u64 acc2[8][4] = {};

    for (int k0 = 0; k0 < DD; k0 += 16) {
        #pragma unroll
        for (int p = 0; p < 2; p++) {
            int m = lm + p * 64;
            float4 v = *(const float4*)&X[(m0 + m) * DD + k0 + lk];
            Xs[lk + 0][m] = v.x;
            Xs[lk + 1][m] = v.y;
            Xs[lk + 2][m] = v.z;
            Xs[lk + 3][m] = v.w;
        }
        #pragma unroll
        for (int p = 0; p < 2; p++) {
            int r = wr + p * 8;
            *(float4*)&Ws[r][wc] = *(const float4*)&W[(k0 + r) * N + n0 + wc];
        }
        __syncthreads();
        #pragma unroll
        for (int kk = 0; kk < 16; kk++) {
            float a[8];
            *(float4*)&a[0] = *(float4*)&Xs[kk][ty * 8];
            *(float4*)&a[4] = *(float4*)&Xs[kk][ty * 8 + 4];
            ulonglong2 t0 = *(ulonglong2*)&Ws[kk][tx * 8];
            ulonglong2 t1 = *(ulonglong2*)&Ws[kk][tx * 8 + 4];
            u64 b2[4] = {t0.x, t0.y, t1.x, t1.y};
            #pragma unroll
            for (int i = 0; i < 8; i++) {
                u64 ai = pk2(a[i], a[i]);
                #pragma unroll
                for (int j = 0; j < 4; j++) ffma2(acc2[i][j], ai, b2[j]);
            }
        }
        __syncthreads();
    }

    float bv8[8];
    #pragma unroll
    for (int j = 0; j < 8; j++) bv8[j] = bias[n0 + tx * 8 + j];
    #pragma unroll
    for (int i = 0; i < 8; i++) {
        int m = m0 + ty * 8 + i;
        float acc[8];
        #pragma unroll
        for (int j = 0; j < 4; j++) upk2(acc[2*j], acc[2*j+1], acc2[i][j]);
        #pragma unroll
        for (int j = 0; j < 8; j++) acc[j] += bv8[j];
        *(float4*)&out[m * N + n0 + tx * 8]     = *(float4*)&acc[0];
        *(float4*)&out[m * N + n0 + tx * 8 + 4] = *(float4*)&acc[4];
    }
}

// ---------------------------------------------------------------------------
// Kernel 1b: row sum-of-squares for Q and K (8192 rows each, 128 cols)
// ---------------------------------------------------------------------------
__global__ __launch_bounds__(256) void sumsq_kernel()
{
    int r = blockIdx.x * 256 + threadIdx.x;       // 0 .. 2*MM-1
    const float* src = (r < MM) ? &g_Q[r * DQKC] : &g_K[(r - MM) * DQKC];
    float s = 0.0f;
    #pragma unroll
    for (int k = 0; k < DQKC; k += 4) {
        float4 v = *(const float4*)&src[k];
        s = fmaf(v.x, v.x, s); s = fmaf(v.y, v.y, s);
        s = fmaf(v.z, v.z, s); s = fmaf(v.w, v.w, s);
    }
    if (r < MM) g_Q2[r] = s; else g_K2[r - MM] = s;
}

// ---------------------------------------------------------------------------
// Kernel 2: Shepard attention, flash-style streaming (f32x2 packed).
// One block per (batch, 64-row q-tile). 256 threads.
// ---------------------------------------------------------------------------
#define QS_STRIDE 68
#define ATT_SMEM_FLOATS (128*QS_STRIDE + 128*QS_STRIDE + 64*256 + 64*QS_STRIDE + 64 + 64 + 64)
#define ATT_SMEM_BYTES  (ATT_SMEM_FLOATS * 4)

__global__ __launch_bounds__(256) void attn_kernel()
{
    extern __shared__ float sm[];
    float* QsT  = sm;                          // [128][68]  QsT[k][q]
    float* KsT  = QsT + 128 * QS_STRIDE;       // [128][68]  KsT[k][c]
    float* Vs   = KsT + 128 * QS_STRIDE;       // [64][256]
    float* wT   = Vs  + 64 * 256;              // [64][68]   wT[key][q]
    float* q2   = wT  + 64 * QS_STRIDE;        // [64]
    float* k2   = q2  + 64;                    // [64]
    float* wsum = k2  + 64;                    // [64]

    const int tid   = threadIdx.x;
    const int b     = blockIdx.x >> 5;
    const int qt    = blockIdx.x & 31;
    const int qrow0 = b * SS + qt * 64;
    const int krow0 = b * SS;

    // Load Q tile transposed + q2 + wsum init (ordered by the chunk-load sync)
    for (int i = tid; i < 64 * 32; i += 256) {
        int r = i & 63, kg = i >> 6;
        float4 v = *(const float4*)&g_Q[(qrow0 + r) * DQKC + kg * 4];
        QsT[(kg * 4 + 0) * QS_STRIDE + r] = v.x;
        QsT[(kg * 4 + 1) * QS_STRIDE + r] = v.y;
        QsT[(kg * 4 + 2) * QS_STRIDE + r] = v.z;
        QsT[(kg * 4 + 3) * QS_STRIDE + r] = v.w;
    }
    if (tid < 64) { wsum[tid] = 0.0f; q2[tid] = g_Q2[qrow0 + tid]; }

    u64 acc2[8][4] = {};   // w@V accumulator, packed

    const int r0p1 = (tid >> 4) * 4, c0p1 = (tid & 15) * 4;   // phase-1 microtile
    const int r0p2 = (tid >> 5) * 8, c0p2 = (tid & 31) * 8;   // phase-2 microtile

    for (int kc = 0; kc < 32; kc++) {
        const int kbase = krow0 + kc * 64;
        // Load K chunk transposed
        for (int i = tid; i < 64 * 32; i += 256) {
            int r = i & 63, kg = i >> 6;
            float4 v = *(const float4*)&g_K[(kbase + r) * DQKC + kg * 4];
            KsT[(kg * 4 + 0) * QS_STRIDE + r] = v.x;
            KsT[(kg * 4 + 1) * QS_STRIDE + r] = v.y;
            KsT[(kg * 4 + 2) * QS_STRIDE + r] = v.z;
            KsT[(kg * 4 + 3) * QS_STRIDE + r] = v.w;
        }
        // Load V chunk (row-major)
        for (int i = tid; i < 64 * 64; i += 256) {
            int r = i >> 6, cg = i & 63;
            *(float4*)&Vs[r * 256 + cg * 4] =
                *(const float4*)&g_V[(kbase + r) * DVC + cg * 4];
        }
        if (tid < 64) k2[tid] = g_K2[kbase + tid];
        __syncthreads();

        // Phase 1: s = Q @ K^T (packed), then w = 1/max(d2, 1e-16)
        {
            u64 sacc2[4][2] = {};
            #pragma unroll 4
            for (int kk = 0; kk < 128; kk++) {
                float4 qv = *(float4*)&QsT[kk * QS_STRIDE + r0p1];
                ulonglong2 kv = *(ulonglong2*)&KsT[kk * QS_STRIDE + c0p1];
                float qa[4] = {qv.x, qv.y, qv.z, qv.w};
                #pragma unroll
                for (int i = 0; i < 4; i++) {
                    u64 qi = pk2(qa[i], qa[i]);
                    ffma2(sacc2[i][0], qi, kv.x);
                    ffma2(sacc2[i][1], qi, kv.y);
                }
            }
            float q2l[4], k2l[4], rsum[4] = {};
            #pragma unroll
            for (int i = 0; i < 4; i++) q2l[i] = q2[r0p1 + i];
            #pragma unroll
            for (int j = 0; j < 4; j++) k2l[j] = k2[c0p1 + j];
            #pragma unroll
            for (int i = 0; i < 4; i++) {
                float s[4];
                upk2(s[0], s[1], sacc2[i][0]);
                upk2(s[2], s[3], sacc2[i][1]);
                #pragma unroll
                for (int j = 0; j < 4; j++) {
                    float d2 = q2l[i] + k2l[j] - 2.0f * s[j];
                    d2 = fmaxf(d2, 0.0f);
                    float w = 1.0f / fmaxf(d2, 1e-16f);
                    wT[(c0p1 + j) * QS_STRIDE + (r0p1 + i)] = w;
                    rsum[i] += w;
                }
            }
            #pragma unroll
            for (int i = 0; i < 4; i++) atomicAdd(&wsum[r0p1 + i], rsum[i]);
        }
        __syncthreads();

        // Phase 2: acc += w @ V (packed)
        #pragma unroll 4
        for (int kk = 0; kk < 64; kk++) {
            float w[8];
            *(float4*)&w[0] = *(float4*)&wT[kk * QS_STRIDE + r0p2];
            *(float4*)&w[4] = *(float4*)&wT[kk * QS_STRIDE + r0p2 + 4];
            ulonglong2 v0 = *(ulonglong2*)&Vs[kk * 256 + c0p2];
            ulonglong2 v1 = *(ulonglong2*)&Vs[kk * 256 + c0p2 + 4];
            u64 b2[4] = {v0.x, v0.y, v1.x, v1.y};
            #pragma unroll
            for (int i = 0; i < 8; i++) {
                u64 wi = pk2(w[i], w[i]);
                #pragma unroll
                for (int j = 0; j < 4; j++) ffma2(acc2[i][j], wi, b2[j]);
            }
        }
        __syncthreads();
    }

    // Normalize and store
    float inv[8];
    #pragma unroll
    for (int i = 0; i < 8; i++) inv[i] = 1.0f / wsum[r0p2 + i];
    #pragma unroll
    for (int i = 0; i < 8; i++) {
        int m = qrow0 + r0p2 + i;
        float acc[8];
        #pragma unroll
        for (int j = 0; j < 4; j++) upk2(acc[2*j], acc[2*j+1], acc2[i][j]);
        #pragma unroll
        for (int j = 0; j < 8; j++) acc[j] *= inv[i];
        *(float4*)&g_AV[m * DVC + c0p2]     = *(float4*)&acc[0];
        *(float4*)&g_AV[m * DVC + c0p2 + 4] = *(float4*)&acc[4];
    }
}

// ---------------------------------------------------------------------------
// Kernel 3: out = X + (AV .* G) @ Wp + bp  (f32x2 packed)
// ---------------------------------------------------------------------------
__global__ __launch_bounds__(256) void out_kernel(
    const float* __restrict__ X,
    const float* __restrict__ Wp, const float* __restrict__ bp,
    float* __restrict__ out)
{
    __shared__ float As[16][132];   // transposed: As[k][m]
    __shared__ float Bs[16][132];

    const int m0  = blockIdx.x * 128;
    const int n0  = blockIdx.y * 128;
    const int tid = threadIdx.x;
    const int tx  = tid & 15, ty = tid >> 4;
    const int lm  = tid >> 2, lk = (tid & 3) * 4;
    const int wr  = tid >> 5, wc = (tid & 31) * 4;

    u64 acc2[8][4] = {};

    for (int k0 = 0; k0 < DVC; k0 += 16) {
        #pragma unroll
        for (int p = 0; p < 2; p++) {
            int m = lm + p * 64;
            float4 a = *(const float4*)&g_AV[(m0 + m) * DVC + k0 + lk];
            float4 g = *(const float4*)&g_G[(m0 + m) * DVC + k0 + lk];
            As[lk + 0][m] = a.x * g.x;
            As[lk + 1][m] = a.y * g.y;
            As[lk + 2][m] = a.z * g.z;
            As[lk + 3][m] = a.w * g.w;
        }
        #pragma unroll
        for (int p = 0; p < 2; p++) {
            int r = wr + p * 8;
            *(float4*)&Bs[r][wc] = *(const float4*)&Wp[(k0 + r) * DD + n0 + wc];
        }
        __syncthreads();
        #pragma unroll
        for (int kk = 0; kk < 16; kk++) {
            float a[8];
            *(float4*)&a[0] = *(float4*)&As[kk][ty * 8];
            *(float4*)&a[4] = *(float4*)&As[kk][ty * 8 + 4];
            ulonglong2 t0 = *(ulonglong2*)&Bs[kk][tx * 8];
            ulonglong2 t1 = *(ulonglong2*)&Bs[kk][tx * 8 + 4];
            u64 b2[4] = {t0.x, t0.y, t1.x, t1.y};
            #pragma unroll
            for (int i = 0; i < 8; i++) {
                u64 ai = pk2(a[i], a[i]);
                #pragma unroll
                for (int j = 0; j < 4; j++) ffma2(acc2[i][j], ai, b2[j]);
            }
        }
        __syncthreads();
    }

    float bv8[8];
    #pragma unroll
    for (int j = 0; j < 8; j++) bv8[j] = bp[n0 + tx * 8 + j];
    #pragma unroll
    for (int i = 0; i < 8; i++) {
        int m = m0 + ty * 8 + i;
        float acc[8];
        #pragma unroll
        for (int j = 0; j < 4; j++) upk2(acc[2*j], acc[2*j+1], acc2[i][j]);
        float4 x0 = *(const float4*)&X[m * DD + n0 + tx * 8];
        float4 x1 = *(const float4*)&X[m * DD + n0 + tx * 8 + 4];
        acc[0] += bv8[0] + x0.x;  acc[1] += bv8[1] + x0.y;
        acc[2] += bv8[2] + x0.z;  acc[3] += bv8[3] + x0.w;
        acc[4] += bv8[4] + x1.x;  acc[5] += bv8[5] + x1.y;
        acc[6] += bv8[6] + x1.z;  acc[7] += bv8[7] + x1.w;
        *(float4*)&out[m * DD + n0 + tx * 8]     = *(float4*)&acc[0];
        *(float4*)&out[m * DD + n0 + tx * 8 + 4] = *(float4*)&acc[4];
    }
}

// ---------------------------------------------------------------------------
extern "C" void kernel_launch(void* const* d_in, const int* in_sizes, int n_in,
                              void* d_out, int out_size)
{
    const float* X  = (const float*)d_in[0];
    const float* Wq = (const float*)d_in[1];
    const float* bq = (const float*)d_in[2];
    const float* Wk = (const float*)d_in[3];
    const float* bk = (const float*)d_in[4];
    const float* Wv = (const float*)d_in[5];
    const float* bv = (const float*)d_in[6];
    const float* Wg = (const float*)d_in[7];
    const float* bg = (const float*)d_in[8];
    const float* Wp = (const float*)d_in[9];
    const float* bp = (const float*)d_in[10];
    float* out = (float*)d_out;

    cudaFuncSetAttribute(attn_kernel,
                         cudaFuncAttributeMaxDynamicSharedMemorySize,
                         ATT_SMEM_BYTES);

    proj_kernel<<<dim3(64, 6), 256>>>(X, Wq, bq, Wk, bk, Wv, bv, Wg, bg);
    sumsq_kernel<<<64, 256>>>();
    attn_kernel<<<128, 256, ATT_SMEM_BYTES>>>();
    out_kernel<<<dim3(64, 8), 256>>>(X, Wp, bp, out);
}

// round 4
// speedup vs baseline: 1.4405x; 1.4405x over previous
#include <cuda_runtime.h>
#include <cuda_bf16.h>
#include <cstdint>

#define BB   4
#define SS   2048
#define DD   1024
#define DQKC 128
#define DVC  256
#define MM   (BB * SS)   // 8192
#define NPROJ 768        // Q(128) K(128) V(256) G(256) transposed-weight rows

// ---------------------------------------------------------------------------
// Device scratch (no allocation allowed)
// ---------------------------------------------------------------------------
__device__ __align__(256) __nv_bfloat16 g_Xhi[MM * DD];
__device__ __align__(256) __nv_bfloat16 g_Xlo[MM * DD];
__device__ __align__(256) __nv_bfloat16 g_Wthi[NPROJ * DD];   // [n][k] (W^T)
__device__ __align__(256) __nv_bfloat16 g_Wtlo[NPROJ * DD];
__device__ __align__(256) __nv_bfloat16 g_Wpthi[DD * DVC];    // [n][k] (Wp^T)
__device__ __align__(256) __nv_bfloat16 g_Wptlo[DD * DVC];
__device__ __align__(256) __nv_bfloat16 g_Phi[MM * DVC];      // (AV*G) hi
__device__ __align__(256) __nv_bfloat16 g_Plo[MM * DVC];      // (AV*G) lo
__device__ __align__(256) float g_Q[MM * DQKC];
__device__ __align__(256) float g_K[MM * DQKC];
__device__ __align__(256) float g_V[MM * DVC];
__device__ __align__(256) float g_G[MM * DVC];
__device__ __align__(256) float g_Q2[MM];
__device__ __align__(256) float g_K2[MM];

// ---------------------------------------------------------------------------
// PTX helpers (baseline ISA only: mma.sync / ldmatrix / cp.async)
// ---------------------------------------------------------------------------
__device__ __forceinline__ uint32_t smem_u32(const void* p) {
    uint32_t a;
    asm("{ .reg .u64 t; cvta.to.shared.u64 t, %1; cvt.u32.u64 %0, t; }"
        : "=r"(a) : "l"(p));
    return a;
}

#define LDSM4(r, addr) \
    asm volatile("ldmatrix.sync.aligned.m8n8.x4.shared.b16 {%0,%1,%2,%3}, [%4];" \
        : "=r"((r)[0]), "=r"((r)[1]), "=r"((r)[2]), "=r"((r)[3]) : "r"(addr))

#define MMA16816(c, a, b0, b1) \
    asm volatile("mma.sync.aligned.m16n8k16.row.col.f32.bf16.bf16.f32 " \
        "{%0,%1,%2,%3}, {%4,%5,%6,%7}, {%8,%9}, {%0,%1,%2,%3};" \
        : "+f"((c)[0]), "+f"((c)[1]), "+f"((c)[2]), "+f"((c)[3]) \
        : "r"((a)[0]), "r"((a)[1]), "r"((a)[2]), "r"((a)[3]), "r"(b0), "r"(b1))

#define CPA16(s, g) \
    asm volatile("cp.async.ca.shared.global [%0], [%1], 16;" :: "r"(s), "l"(g) : "memory")
#define CP_COMMIT() asm volatile("cp.async.commit_group;" ::: "memory")
#define CP_WAIT1()  asm volatile("cp.async.wait_group 1;" ::: "memory")
#define CP_WAIT0()  asm volatile("cp.async.wait_group 0;" ::: "memory")

// SMEM layout (per stage): 4 tiles of 128 rows x 80B (pitch 40 bf16)
#define TILE_BYTES   10240          // 128 * 80
#define STAGE_BYTES  (4 * TILE_BYTES)
#define GEMM_SMEM_BYTES (2 * STAGE_BYTES)   // 81920

// ---------------------------------------------------------------------------
// Prep kernels: split fp32 -> bf16 hi/lo (hi = rn(x), lo = rn(x - hi))
// ---------------------------------------------------------------------------
__global__ __launch_bounds__(256) void split_x_kernel(const float* __restrict__ X)
{
    int i = (blockIdx.x * 256 + threadIdx.x) * 4;
    float4 v = *(const float4*)&X[i];
    float p[4] = {v.x, v.y, v.z, v.w};
    __nv_bfloat16 h[4], l[4];
    #pragma unroll
    for (int j = 0; j < 4; j++) {
        h[j] = __float2bfloat16(p[j]);
        l[j] = __float2bfloat16(p[j] - __bfloat162float(h[j]));
    }
    *(__nv_bfloat162*)&g_Xhi[i]     = __nv_bfloat162(h[0], h[1]);
    *(__nv_bfloat162*)&g_Xhi[i + 2] = __nv_bfloat162(h[2], h[3]);
    *(__nv_bfloat162*)&g_Xlo[i]     = __nv_bfloat162(l[0], l[1]);
    *(__nv_bfloat162*)&g_Xlo[i + 2] = __nv_bfloat162(l[2], l[3]);
}

__global__ __launch_bounds__(256) void split_w_kernel(
    const float* __restrict__ Wq, const float* __restrict__ Wk,
    const float* __restrict__ Wv, const float* __restrict__ Wg,
    const float* __restrict__ Wp)
{
    int idx = blockIdx.x * 256 + threadIdx.x;
    float x;
    __nv_bfloat16* hi;
    __nv_bfloat16* lo;
    int off;
    if (idx < NPROJ * DD) {
        int n = idx >> 10, k = idx & 1023;
        const float* W; int col; int ncols;
        if (n < 128)      { W = Wq; col = n;       ncols = 128; }
        else if (n < 256) { W = Wk; col = n - 128; ncols = 128; }
        else if (n < 512) { W = Wv; col = n - 256; ncols = 256; }
        else              { W = Wg; col = n - 512; ncols = 256; }
        x = W[k * ncols + col];
        hi = g_Wthi; lo = g_Wtlo; off = idx;
    } else {
        int j = idx - NPROJ * DD;
        int n = j >> 8, k = j & 255;
        x = Wp[k * DD + n];
        hi = g_Wpthi; lo = g_Wptlo; off = j;
    }
    __nv_bfloat16 h = __float2bfloat16(x);
    hi[off] = h;
    lo[off] = __float2bfloat16(x - __bfloat162float(h));
}

// ---------------------------------------------------------------------------
// Shared GEMM machinery (split-bf16, mma.sync, double-buffered cp.async)
// ---------------------------------------------------------------------------
__device__ __forceinline__ void stage_copy(
    uint32_t sstage,
    const __nv_bfloat16* __restrict__ Ahi, const __nv_bfloat16* __restrict__ Alo, int lda,
    const __nv_bfloat16* __restrict__ Bhi, const __nv_bfloat16* __restrict__ Blo, int ldb,
    int k0, int tid)
{
    #pragma unroll
    for (int i = 0; i < 2; i++) {
        int c = tid + i * 256;              // 0..511
        int row = c >> 2;
        int seg = c & 3;
        uint32_t so = row * 80 + seg * 16;
        size_t ga = (size_t)row * lda + k0 + seg * 8;
        size_t gb = (size_t)row * ldb + k0 + seg * 8;
        CPA16(sstage +                 so, Ahi + ga);
        CPA16(sstage +     TILE_BYTES + so, Alo + ga);
        CPA16(sstage + 2 * TILE_BYTES + so, Bhi + gb);
        CPA16(sstage + 3 * TILE_BYTES + so, Blo + gb);
    }
}

__device__ __forceinline__ void compute_stage(
    uint32_t sstage, uint32_t a_off, uint32_t b_off, float acc[4][4][4])
{
    #pragma unroll
    for (int ks = 0; ks < 2; ks++) {
        uint32_t ah[4][4], al[4][4], bh[2][4], bl[2][4];
        #pragma unroll
        for (int mf = 0; mf < 4; mf++) {
            LDSM4(ah[mf], sstage +              a_off + mf * 1280 + ks * 32);
            LDSM4(al[mf], sstage + TILE_BYTES + a_off + mf * 1280 + ks * 32);
        }
        #pragma unroll
        for (int np = 0; np < 2; np++) {
            LDSM4(bh[np], sstage + 2 * TILE_BYTES + b_off + np * 1280 + ks * 32);
            LDSM4(bl[np], sstage + 3 * TILE_BYTES + b_off + np * 1280 + ks * 32);
        }
        #pragma unroll
        for (int mf = 0; mf < 4; mf++) {
            #pragma unroll
            for (int nf = 0; nf < 4; nf++) {
                uint32_t b0h = bh[nf >> 1][(nf & 1) * 2], b1h = bh[nf >> 1][(nf & 1) * 2 + 1];
                uint32_t b0l = bl[nf >> 1][(nf & 1) * 2], b1l = bl[nf >> 1][(nf & 1) * 2 + 1];
                MMA16816(acc[mf][nf], ah[mf], b0h, b1h);
                MMA16816(acc[mf][nf], ah[mf], b0l, b1l);
                MMA16816(acc[mf][nf], al[mf], b0h, b1h);
            }
        }
    }
}

// ---------------------------------------------------------------------------
// proj_gemm: grid (64, 6), 256 threads.  Y[slab] = X @ W + b
// slabs: 0=Q 1=K 2=V[:128] 3=V[128:] 4=G[:128] 5=G[128:]
// ---------------------------------------------------------------------------
__global__ __launch_bounds__(256) void proj_gemm(
    const float* __restrict__ bq, const float* __restrict__ bk,
    const float* __restrict__ bv, const float* __restrict__ bg)
{
    extern __shared__ char smraw[];
    uint32_t sbase = smem_u32(smraw);
    const int tid = threadIdx.x;
    const int m0 = blockIdx.x * 128;
    const int slab = blockIdx.y;
    const int nbase = slab * 128;

    const __nv_bfloat16* Ahi = g_Xhi + (size_t)m0 * DD;
    const __nv_bfloat16* Alo = g_Xlo + (size_t)m0 * DD;
    const __nv_bfloat16* Bhi = g_Wthi + (size_t)nbase * DD;
    const __nv_bfloat16* Blo = g_Wtlo + (size_t)nbase * DD;

    const int warp = tid >> 5, lane = tid & 31;
    const int lr = lane & 7, gq = lane >> 3;
    const int wm = (warp & 1) * 64, wn = (warp >> 1) * 32;
    const uint32_t a_off = (wm + lr + (gq & 1) * 8) * 80 + (gq >> 1) * 16;
    const uint32_t b_off = (wn + lr + (gq >> 1) * 8) * 80 + (gq & 1) * 16;

    float acc[4][4][4] = {};

    stage_copy(sbase, Ahi, Alo, DD, Bhi, Blo, DD, 0, tid);
    CP_COMMIT();
    for (int kb = 0; kb < 32; kb++) {
        if (kb + 1 < 32) {
            stage_copy(sbase + ((kb + 1) & 1) * STAGE_BYTES,
                       Ahi, Alo, DD, Bhi, Blo, DD, (kb + 1) * 32, tid);
            CP_COMMIT();
            CP_WAIT1();
        } else {
            CP_WAIT0();
        }
        __syncthreads();
        compute_stage(sbase + (kb & 1) * STAGE_BYTES, a_off, b_off, acc);
        __syncthreads();
    }

    const float* bias; float* outp; int outN; int nb_off = 0;
    switch (slab) {
        case 0:  bias = bq; outp = g_Q; outN = DQKC; break;
        case 1:  bias = bk; outp = g_K; outN = DQKC; break;
        case 2:  bias = bv; outp = g_V; outN = DVC;  break;
        case 3:  bias = bv; outp = g_V; outN = DVC;  nb_off = 128; break;
        case 4:  bias = bg; outp = g_G; outN = DVC;  break;
        default: bias = bg; outp = g_G; outN = DVC;  nb_off = 128; break;
    }
    const int mrow = lane >> 2, ncol = (lane & 3) * 2;
    #pragma unroll
    for (int mf = 0; mf < 4; mf++) {
        #pragma unroll
        for (int nf = 0; nf < 4; nf++) {
            int m = m0 + wm + mf * 16 + mrow;
            int n = nb_off + wn + nf * 8 + ncol;
            float b0 = bias[n], b1 = bias[n + 1];
            *(float2*)&outp[(size_t)m * outN + n] =
                make_float2(acc[mf][nf][0] + b0, acc[mf][nf][1] + b1);
            *(float2*)&outp[(size_t)(m + 8) * outN + n] =
                make_float2(acc[mf][nf][2] + b0, acc[mf][nf][3] + b1);
        }
    }
}

// ---------------------------------------------------------------------------
// sumsq: row sum-of-squares for Q and K
// ---------------------------------------------------------------------------
__global__ __launch_bounds__(256) void sumsq_kernel()
{
    int r = blockIdx.x * 256 + threadIdx.x;       // 0 .. 2*MM-1
    const float* src = (r < MM) ? &g_Q[r * DQKC] : &g_K[(r - MM) * DQKC];
    float s = 0.0f;
    #pragma unroll
    for (int k = 0; k < DQKC; k += 4) {
        float4 v = *(const float4*)&src[k];
        s = fmaf(v.x, v.x, s); s = fmaf(v.y, v.y, s);
        s = fmaf(v.z, v.z, s); s = fmaf(v.w, v.w, s);
    }
    if (r < MM) g_Q2[r] = s; else g_K2[r - MM] = s;
}

// ---------------------------------------------------------------------------
// Kernel 2: Shepard attention (fp32 SIMT, R1 core) — epilogue now gates with
// G and writes split-bf16 (AV*G) directly for out_gemm.
// ---------------------------------------------------------------------------
#define QS_STRIDE 68
#define ATT_SMEM_FLOATS (128*QS_STRIDE + 128*QS_STRIDE + 64*256 + 64*QS_STRIDE + 64 + 64 + 64)
#define ATT_SMEM_BYTES  (ATT_SMEM_FLOATS * 4)

__global__ __launch_bounds__(256) void attn_kernel()
{
    extern __shared__ float sm[];
    float* QsT  = sm;
    float* KsT  = QsT + 128 * QS_STRIDE;
    float* Vs   = KsT + 128 * QS_STRIDE;
    float* wT   = Vs  + 64 * 256;
    float* q2   = wT  + 64 * QS_STRIDE;
    float* k2   = q2  + 64;
    float* wsum = k2  + 64;

    const int tid   = threadIdx.x;
    const int b     = blockIdx.x >> 5;
    const int qt    = blockIdx.x & 31;
    const int qrow0 = b * SS + qt * 64;
    const int krow0 = b * SS;

    for (int i = tid; i < 64 * 32; i += 256) {
        int r = i & 63, kg = i >> 6;
        float4 v = *(const float4*)&g_Q[(qrow0 + r) * DQKC + kg * 4];
        QsT[(kg * 4 + 0) * QS_STRIDE + r] = v.x;
        QsT[(kg * 4 + 1) * QS_STRIDE + r] = v.y;
        QsT[(kg * 4 + 2) * QS_STRIDE + r] = v.z;
        QsT[(kg * 4 + 3) * QS_STRIDE + r] = v.w;
    }
    if (tid < 64) { wsum[tid] = 0.0f; q2[tid] = g_Q2[qrow0 + tid]; }

    float acc[8][8] = {};

    const int r0p1 = (tid >> 4) * 4, c0p1 = (tid & 15) * 4;
    const int r0p2 = (tid >> 5) * 8, c0p2 = (tid & 31) * 8;

    for (int kc = 0; kc < 32; kc++) {
        const int kbase = krow0 + kc * 64;
        for (int i = tid; i < 64 * 32; i += 256) {
            int r = i & 63, kg = i >> 6;
            float4 v = *(const float4*)&g_K[(kbase + r) * DQKC + kg * 4];
            KsT[(kg * 4 + 0) * QS_STRIDE + r] = v.x;
            KsT[(kg * 4 + 1) * QS_STRIDE + r] = v.y;
            KsT[(kg * 4 + 2) * QS_STRIDE + r] = v.z;
            KsT[(kg * 4 + 3) * QS_STRIDE + r] = v.w;
        }
        for (int i = tid; i < 64 * 64; i += 256) {
            int r = i >> 6, cg = i & 63;
            *(float4*)&Vs[r * 256 + cg * 4] =
                *(const float4*)&g_V[(kbase + r) * DVC + cg * 4];
        }
        if (tid < 64) k2[tid] = g_K2[kbase + tid];
        __syncthreads();

        {
            float sacc[4][4] = {};
            #pragma unroll 4
            for (int kk = 0; kk < 128; kk++) {
                float4 qv = *(float4*)&QsT[kk * QS_STRIDE + r0p1];
                float4 kv = *(float4*)&KsT[kk * QS_STRIDE + c0p1];
                float qa[4] = {qv.x, qv.y, qv.z, qv.w};
                float ka[4] = {kv.x, kv.y, kv.z, kv.w};
                #pragma unroll
                for (int i = 0; i < 4; i++)
                    #pragma unroll
                    for (int j = 0; j < 4; j++)
                        sacc[i][j] = fmaf(qa[i], ka[j], sacc[i][j]);
            }
            float q2l[4], k2l[4], rsum[4] = {};
            #pragma unroll
            for (int i = 0; i < 4; i++) q2l[i] = q2[r0p1 + i];
            #pragma unroll
            for (int j = 0; j < 4; j++) k2l[j] = k2[c0p1 + j];
            #pragma unroll
            for (int i = 0; i < 4; i++) {
                #pragma unroll
                for (int j = 0; j < 4; j++) {
                    float d2 = q2l[i] + k2l[j] - 2.0f * sacc[i][j];
                    d2 = fmaxf(d2, 0.0f);
                    float w = 1.0f / fmaxf(d2, 1e-16f);
                    wT[(c0p1 + j) * QS_STRIDE + (r0p1 + i)] = w;
                    rsum[i] += w;
                }
            }
            #pragma unroll
            for (int i = 0; i < 4; i++) atomicAdd(&wsum[r0p1 + i], rsum[i]);
        }
        __syncthreads();

        #pragma unroll 4
        for (int kk = 0; kk < 64; kk++) {
            float w[8], v[8];
            *(float4*)&w[0] = *(float4*)&wT[kk * QS_STRIDE + r0p2];
            *(float4*)&w[4] = *(float4*)&wT[kk * QS_STRIDE + r0p2 + 4];
            *(float4*)&v[0] = *(float4*)&Vs[kk * 256 + c0p2];
            *(float4*)&v[4] = *(float4*)&Vs[kk * 256 + c0p2 + 4];
            #pragma unroll
            for (int i = 0; i < 8; i++)
                #pragma unroll
                for (int j = 0; j < 8; j++)
                    acc[i][j] = fmaf(w[i], v[j], acc[i][j]);
        }
        __syncthreads();
    }

    // Epilogue: normalize, gate with G, split to bf16 hi/lo
    float inv[8];
    #pragma unroll
    for (int i = 0; i < 8; i++) inv[i] = 1.0f / wsum[r0p2 + i];
    #pragma unroll
    for (int i = 0; i < 8; i++) {
        int m = qrow0 + r0p2 + i;
        float4 g0 = *(const float4*)&g_G[(size_t)m * DVC + c0p2];
        float4 g1 = *(const float4*)&g_G[(size_t)m * DVC + c0p2 + 4];
        float gg[8] = {g0.x, g0.y, g0.z, g0.w, g1.x, g1.y, g1.z, g1.w};
        uint32_t hw[4], lw[4];
        #pragma unroll
        for (int j = 0; j < 4; j++) {
            float p0 = acc[i][2*j]     * inv[i] * gg[2*j];
            float p1 = acc[i][2*j + 1] * inv[i] * gg[2*j + 1];
            __nv_bfloat16 h0 = __float2bfloat16(p0);
            __nv_bfloat16 h1 = __float2bfloat16(p1);
            __nv_bfloat16 l0 = __float2bfloat16(p0 - __bfloat162float(h0));
            __nv_bfloat16 l1 = __float2bfloat16(p1 - __bfloat162float(h1));
            __nv_bfloat162 hp(h0, h1), lp(l0, l1);
            hw[j] = *reinterpret_cast<uint32_t*>(&hp);
            lw[j] = *reinterpret_cast<uint32_t*>(&lp);
        }
        *(uint4*)&g_Phi[(size_t)m * DVC + c0p2] = make_uint4(hw[0], hw[1], hw[2], hw[3]);
        *(uint4*)&g_Plo[(size_t)m * DVC + c0p2] = make_uint4(lw[0], lw[1], lw[2], lw[3]);
    }
}

// ---------------------------------------------------------------------------
// out_gemm: grid (64, 8), 256 threads.  out = X + P @ Wp + bp,  P = AV*G
// ---------------------------------------------------------------------------
__global__ __launch_bounds__(256) void out_gemm(
    const float* __restrict__ X, const float* __restrict__ bp,
    float* __restrict__ outp)
{
    extern __shared__ char smraw[];
    uint32_t sbase = smem_u32(smraw);
    const int tid = threadIdx.x;
    const int m0 = blockIdx.x * 128;
    const int n0 = blockIdx.y * 128;

    const __nv_bfloat16* Ahi = g_Phi + (size_t)m0 * DVC;
    const __nv_bfloat16* Alo = g_Plo + (size_t)m0 * DVC;
    const __nv_bfloat16* Bhi = g_Wpthi + (size_t)n0 * DVC;
    const __nv_bfloat16* Blo = g_Wptlo + (size_t)n0 * DVC;

    const int warp = tid >> 5, lane = tid & 31;
    const int lr = lane & 7, gq = lane >> 3;
    const int wm = (warp & 1) * 64, wn = (warp >> 1) * 32;
    const uint32_t a_off = (wm + lr + (gq & 1) * 8) * 80 + (gq >> 1) * 16;
    const uint32_t b_off = (wn + lr + (gq >> 1) * 8) * 80 + (gq & 1) * 16;

    float acc[4][4][4] = {};

    stage_copy(sbase, Ahi, Alo, DVC, Bhi, Blo, DVC, 0, tid);
    CP_COMMIT();
    for (int kb = 0; kb < 8; kb++) {
        if (kb + 1 < 8) {
            stage_copy(sbase + ((kb + 1) & 1) * STAGE_BYTES,
                       Ahi, Alo, DVC, Bhi, Blo, DVC, (kb + 1) * 32, tid);
            CP_COMMIT();
            CP_WAIT1();
        } else {
            CP_WAIT0();
        }
        __syncthreads();
        compute_stage(sbase + (kb & 1) * STAGE_BYTES, a_off, b_off, acc);
        __syncthreads();
    }

    const int mrow = lane >> 2, ncol = (lane & 3) * 2;
    #pragma unroll
    for (int mf = 0; mf < 4; mf++) {
        #pragma unroll
        for (int nf = 0; nf < 4; nf++) {
            int m = m0 + wm + mf * 16 + mrow;
            int n = n0 + wn + nf * 8 + ncol;
            float b0 = bp[n], b1 = bp[n + 1];
            float2 x0 = *(const float2*)&X[(size_t)m * DD + n];
            float2 x1 = *(const float2*)&X[(size_t)(m + 8) * DD + n];
            *(float2*)&outp[(size_t)m * DD + n] =
                make_float2(acc[mf][nf][0] + b0 + x0.x, acc[mf][nf][1] + b1 + x0.y);
            *(float2*)&outp[(size_t)(m + 8) * DD + n] =
                make_float2(acc[mf][nf][2] + b0 + x1.x, acc[mf][nf][3] + b1 + x1.y);
        }
    }
}

// ---------------------------------------------------------------------------
extern "C" void kernel_launch(void* const* d_in, const int* in_sizes, int n_in,
                              void* d_out, int out_size)
{
    const float* X  = (const float*)d_in[0];
    const float* Wq = (const float*)d_in[1];
    const float* bq = (const float*)d_in[2];
    const float* Wk = (const float*)d_in[3];
    const float* bk = (const float*)d_in[4];
    const float* Wv = (const float*)d_in[5];
    const float* bv = (const float*)d_in[6];
    const float* Wg = (const float*)d_in[7];
    const float* bg = (const float*)d_in[8];
    const float* Wp = (const float*)d_in[9];
    const float* bp = (const float*)d_in[10];
    float* out = (float*)d_out;

    cudaFuncSetAttribute(proj_gemm, cudaFuncAttributeMaxDynamicSharedMemorySize, GEMM_SMEM_BYTES);
    cudaFuncSetAttribute(out_gemm,  cudaFuncAttributeMaxDynamicSharedMemorySize, GEMM_SMEM_BYTES);
    cudaFuncSetAttribute(attn_kernel, cudaFuncAttributeMaxDynamicSharedMemorySize, ATT_SMEM_BYTES);

    split_x_kernel<<<MM * DD / 1024, 256>>>(X);
    split_w_kernel<<<(NPROJ * DD + DD * DVC) / 256, 256>>>(Wq, Wk, Wv, Wg, Wp);
    proj_gemm<<<dim3(64, 6), 256, GEMM_SMEM_BYTES>>>(bq, bk, bv, bg);
    sumsq_kernel<<<64, 256>>>();
    attn_kernel<<<128, 256, ATT_SMEM_BYTES>>>();
    out_gemm<<<dim3(64, 8), 256, GEMM_SMEM_BYTES>>>(X, bp, out);
}

// round 5
// speedup vs baseline: 2.4733x; 1.7169x over previous
#include <cuda_runtime.h>
#include <cuda_bf16.h>
#include <cstdint>

#define BB   4
#define SS   2048
#define DD   1024
#define DQKC 128
#define DVC  256
#define MM   (BB * SS)   // 8192
#define NPROJ 768

// ---------------------------------------------------------------------------
// Device scratch
// ---------------------------------------------------------------------------
__device__ __align__(256) __nv_bfloat16 g_Xhi[MM * DD];
__device__ __align__(256) __nv_bfloat16 g_Xlo[MM * DD];
__device__ __align__(256) __nv_bfloat16 g_Wthi[NPROJ * DD];
__device__ __align__(256) __nv_bfloat16 g_Wtlo[NPROJ * DD];
__device__ __align__(256) __nv_bfloat16 g_Wpthi[DD * DVC];
__device__ __align__(256) __nv_bfloat16 g_Wptlo[DD * DVC];
__device__ __align__(256) __nv_bfloat16 g_Qhi[MM * DQKC];
__device__ __align__(256) __nv_bfloat16 g_Qlo[MM * DQKC];
__device__ __align__(256) __nv_bfloat16 g_Khi[MM * DQKC];
__device__ __align__(256) __nv_bfloat16 g_Klo[MM * DQKC];
__device__ __align__(256) __nv_bfloat16 g_Vthi[BB * DVC * SS];  // [b][n][s]
__device__ __align__(256) __nv_bfloat16 g_Vtlo[BB * DVC * SS];
__device__ __align__(256) __nv_bfloat16 g_Phi[MM * DVC];        // (AV*G) hi
__device__ __align__(256) __nv_bfloat16 g_Plo[MM * DVC];
__device__ __align__(256) float g_Q[MM * DQKC];
__device__ __align__(256) float g_K[MM * DQKC];
__device__ __align__(256) float g_V[MM * DVC];
__device__ __align__(256) float g_G[MM * DVC];
__device__ __align__(256) float g_Q2[MM];
__device__ __align__(256) float g_K2[MM];

// ---------------------------------------------------------------------------
// PTX helpers (baseline ISA: mma.sync / ldmatrix / cp.async)
// ---------------------------------------------------------------------------
__device__ __forceinline__ uint32_t smem_u32(const void* p) {
    uint32_t a;
    asm("{ .reg .u64 t; cvta.to.shared.u64 t, %1; cvt.u32.u64 %0, t; }"
        : "=r"(a) : "l"(p));
    return a;
}

#define LDSM4(r, addr) \
    asm volatile("ldmatrix.sync.aligned.m8n8.x4.shared.b16 {%0,%1,%2,%3}, [%4];" \
        : "=r"((r)[0]), "=r"((r)[1]), "=r"((r)[2]), "=r"((r)[3]) : "r"(addr))

#define MMA16816(c, a, b0, b1) \
    asm volatile("mma.sync.aligned.m16n8k16.row.col.f32.bf16.bf16.f32 " \
        "{%0,%1,%2,%3}, {%4,%5,%6,%7}, {%8,%9}, {%0,%1,%2,%3};" \
        : "+f"((c)[0]), "+f"((c)[1]), "+f"((c)[2]), "+f"((c)[3]) \
        : "r"((a)[0]), "r"((a)[1]), "r"((a)[2]), "r"((a)[3]), "r"(b0), "r"(b1))

#define CPA16(s, g) \
    asm volatile("cp.async.ca.shared.global [%0], [%1], 16;" :: "r"(s), "l"(g) : "memory")
#define CP_COMMIT() asm volatile("cp.async.commit_group;" ::: "memory")
#define CP_WAIT1()  asm volatile("cp.async.wait_group 1;" ::: "memory")
#define CP_WAIT0()  asm volatile("cp.async.wait_group 0;" ::: "memory")

__device__ __forceinline__ void split2(float a, float b, uint32_t& hw, uint32_t& lw) {
    __nv_bfloat16 ha = __float2bfloat16(a), hb = __float2bfloat16(b);
    __nv_bfloat16 la = __float2bfloat16(a - __bfloat162float(ha));
    __nv_bfloat16 lb = __float2bfloat16(b - __bfloat162float(hb));
    __nv_bfloat162 hp(ha, hb), lp(la, lb);
    hw = *reinterpret_cast<uint32_t*>(&hp);
    lw = *reinterpret_cast<uint32_t*>(&lp);
}

// ---------------------------------------------------------------------------
// Prep: split fp32 -> bf16 hi/lo
// ---------------------------------------------------------------------------
__global__ __launch_bounds__(256) void split_x_kernel(const float* __restrict__ X)
{
    int i = (blockIdx.x * 256 + threadIdx.x) * 4;
    float4 v = *(const float4*)&X[i];
    float p[4] = {v.x, v.y, v.z, v.w};
    uint32_t hw0, lw0, hw1, lw1;
    split2(p[0], p[1], hw0, lw0);
    split2(p[2], p[3], hw1, lw1);
    *(uint2*)&g_Xhi[i] = make_uint2(hw0, hw1);
    *(uint2*)&g_Xlo[i] = make_uint2(lw0, lw1);
}

__global__ __launch_bounds__(256) void split_w_kernel(
    const float* __restrict__ Wq, const float* __restrict__ Wk,
    const float* __restrict__ Wv, const float* __restrict__ Wg,
    const float* __restrict__ Wp)
{
    int idx = blockIdx.x * 256 + threadIdx.x;
    float x;
    __nv_bfloat16* hi;
    __nv_bfloat16* lo;
    int off;
    if (idx < NPROJ * DD) {
        int n = idx >> 10, k = idx & 1023;
        const float* W; int col; int ncols;
        if (n < 128)      { W = Wq; col = n;       ncols = 128; }
        else if (n < 256) { W = Wk; col = n - 128; ncols = 128; }
        else if (n < 512) { W = Wv; col = n - 256; ncols = 256; }
        else              { W = Wg; col = n - 512; ncols = 256; }
        x = W[k * ncols + col];
        hi = g_Wthi; lo = g_Wtlo; off = idx;
    } else {
        int j = idx - NPROJ * DD;
        int n = j >> 8, k = j & 255;
        x = Wp[k * DD + n];
        hi = g_Wpthi; lo = g_Wptlo; off = j;
    }
    __nv_bfloat16 h = __float2bfloat16(x);
    hi[off] = h;
    lo[off] = __float2bfloat16(x - __bfloat162float(h));
}

// ---------------------------------------------------------------------------
// Shared GEMM machinery (R4, proven)
// ---------------------------------------------------------------------------
#define TILE_BYTES   10240
#define STAGE_BYTES  (4 * TILE_BYTES)
#define GEMM_SMEM_BYTES (2 * STAGE_BYTES)

__device__ __forceinline__ void stage_copy(
    uint32_t sstage,
    const __nv_bfloat16* __restrict__ Ahi, const __nv_bfloat16* __restrict__ Alo, int lda,
    const __nv_bfloat16* __restrict__ Bhi, const __nv_bfloat16* __restrict__ Blo, int ldb,
    int k0, int tid)
{
    #pragma unroll
    for (int i = 0; i < 2; i++) {
        int c = tid + i * 256;
        int row = c >> 2;
        int seg = c & 3;
        uint32_t so = row * 80 + seg * 16;
        size_t ga = (size_t)row * lda + k0 + seg * 8;
        size_t gb = (size_t)row * ldb + k0 + seg * 8;
        CPA16(sstage +                 so, Ahi + ga);
        CPA16(sstage +     TILE_BYTES + so, Alo + ga);
        CPA16(sstage + 2 * TILE_BYTES + so, Bhi + gb);
        CPA16(sstage + 3 * TILE_BYTES + so, Blo + gb);
    }
}

__device__ __forceinline__ void compute_stage(
    uint32_t sstage, uint32_t a_off, uint32_t b_off, float acc[4][4][4])
{
    #pragma unroll
    for (int ks = 0; ks < 2; ks++) {
        uint32_t ah[4][4], al[4][4], bh[2][4], bl[2][4];
        #pragma unroll
        for (int mf = 0; mf < 4; mf++) {
            LDSM4(ah[mf], sstage +              a_off + mf * 1280 + ks * 32);
            LDSM4(al[mf], sstage + TILE_BYTES + a_off + mf * 1280 + ks * 32);
        }
        #pragma unroll
        for (int np = 0; np < 2; np++) {
            LDSM4(bh[np], sstage + 2 * TILE_BYTES + b_off + np * 1280 + ks * 32);
            LDSM4(bl[np], sstage + 3 * TILE_BYTES + b_off + np * 1280 + ks * 32);
        }
        #pragma unroll
        for (int mf = 0; mf < 4; mf++) {
            #pragma unroll
            for (int nf = 0; nf < 4; nf++) {
                uint32_t b0h = bh[nf >> 1][(nf & 1) * 2], b1h = bh[nf >> 1][(nf & 1) * 2 + 1];
                uint32_t b0l = bl[nf >> 1][(nf & 1) * 2], b1l = bl[nf >> 1][(nf & 1) * 2 + 1];
                MMA16816(acc[mf][nf], ah[mf], b0h, b1h);
                MMA16816(acc[mf][nf], ah[mf], b0l, b1l);
                MMA16816(acc[mf][nf], al[mf], b0h, b1h);
            }
        }
    }
}

// ---------------------------------------------------------------------------
// proj_gemm: grid (64, 6). Epilogue also emits bf16 hi/lo Q and K.
// ---------------------------------------------------------------------------
__global__ __launch_bounds__(256) void proj_gemm(
    const float* __restrict__ bq, const float* __restrict__ bk,
    const float* __restrict__ bv, const float* __restrict__ bg)
{
    extern __shared__ char smraw[];
    uint32_t sbase = smem_u32(smraw);
    const int tid = threadIdx.x;
    const int m0 = blockIdx.x * 128;
    const int slab = blockIdx.y;
    const int nbase = slab * 128;

    const __nv_bfloat16* Ahi = g_Xhi + (size_t)m0 * DD;
    const __nv_bfloat16* Alo = g_Xlo + (size_t)m0 * DD;
    const __nv_bfloat16* Bhi = g_Wthi + (size_t)nbase * DD;
    const __nv_bfloat16* Blo = g_Wtlo + (size_t)nbase * DD;

    const int warp = tid >> 5, lane = tid & 31;
    const int lr = lane & 7, gq = lane >> 3;
    const int wm = (warp & 1) * 64, wn = (warp >> 1) * 32;
    const uint32_t a_off = (wm + lr + (gq & 1) * 8) * 80 + (gq >> 1) * 16;
    const uint32_t b_off = (wn + lr + (gq >> 1) * 8) * 80 + (gq & 1) * 16;

    float acc[4][4][4] = {};

    stage_copy(sbase, Ahi, Alo, DD, Bhi, Blo, DD, 0, tid);
    CP_COMMIT();
    for (int kb = 0; kb < 32; kb++) {
        if (kb + 1 < 32) {
            stage_copy(sbase + ((kb + 1) & 1) * STAGE_BYTES,
                       Ahi, Alo, DD, Bhi, Blo, DD, (kb + 1) * 32, tid);
            CP_COMMIT();
            CP_WAIT1();
        } else {
            CP_WAIT0();
        }
        __syncthreads();
        compute_stage(sbase + (kb & 1) * STAGE_BYTES, a_off, b_off, acc);
        __syncthreads();
    }

    const float* bias; float* outp; int outN; int nb_off = 0;
    __nv_bfloat16* bfh = nullptr; __nv_bfloat16* bfl = nullptr;
    switch (slab) {
        case 0:  bias = bq; outp = g_Q; outN = DQKC; bfh = g_Qhi; bfl = g_Qlo; break;
        case 1:  bias = bk; outp = g_K; outN = DQKC; bfh = g_Khi; bfl = g_Klo; break;
        case 2:  bias = bv; outp = g_V; outN = DVC;  break;
        case 3:  bias = bv; outp = g_V; outN = DVC;  nb_off = 128; break;
        case 4:  bias = bg; outp = g_G; outN = DVC;  break;
        default: bias = bg; outp = g_G; outN = DVC;  nb_off = 128; break;
    }
    const int mrow = lane >> 2, ncol = (lane & 3) * 2;
    #pragma unroll
    for (int mf = 0; mf < 4; mf++) {
        #pragma unroll
        for (int nf = 0; nf < 4; nf++) {
            int m = m0 + wm + mf * 16 + mrow;
            int n = nb_off + wn + nf * 8 + ncol;
            float b0 = bias[n], b1 = bias[n + 1];
            float v00 = acc[mf][nf][0] + b0, v01 = acc[mf][nf][1] + b1;
            float v10 = acc[mf][nf][2] + b0, v11 = acc[mf][nf][3] + b1;
            *(float2*)&outp[(size_t)m * outN + n] = make_float2(v00, v01);
            *(float2*)&outp[(size_t)(m + 8) * outN + n] = make_float2(v10, v11);
            if (bfh) {
                uint32_t hw, lw;
                split2(v00, v01, hw, lw);
                *(uint32_t*)&bfh[(size_t)m * DQKC + n] = hw;
                *(uint32_t*)&bfl[(size_t)m * DQKC + n] = lw;
                split2(v10, v11, hw, lw);
                *(uint32_t*)&bfh[(size_t)(m + 8) * DQKC + n] = hw;
                *(uint32_t*)&bfl[(size_t)(m + 8) * DQKC + n] = lw;
            }
        }
    }
}

// ---------------------------------------------------------------------------
// sumsq: row sum-of-squares for Q and K
// ---------------------------------------------------------------------------
__global__ __launch_bounds__(256) void sumsq_kernel()
{
    int r = blockIdx.x * 256 + threadIdx.x;
    const float* src = (r < MM) ? &g_Q[r * DQKC] : &g_K[(r - MM) * DQKC];
    float s = 0.0f;
    #pragma unroll
    for (int k = 0; k < DQKC; k += 4) {
        float4 v = *(const float4*)&src[k];
        s = fmaf(v.x, v.x, s); s = fmaf(v.y, v.y, s);
        s = fmaf(v.z, v.z, s); s = fmaf(v.w, v.w, s);
    }
    if (r < MM) g_Q2[r] = s; else g_K2[r - MM] = s;
}

// ---------------------------------------------------------------------------
// vtrans: V[8192][256] fp32 -> Vt[b][n][s] bf16 hi/lo
// ---------------------------------------------------------------------------
__global__ __launch_bounds__(256) void vtrans_kernel()
{
    __shared__ float ts[32][33];
    const int bx = blockIdx.x;   // n tile 0..7
    const int by = blockIdx.y;   // m tile 0..255
    const int tx = threadIdx.x & 31, ty = threadIdx.x >> 5;
    #pragma unroll
    for (int r = 0; r < 4; r++) {
        int m = by * 32 + ty + r * 8;
        ts[ty + r * 8][tx] = g_V[(size_t)m * DVC + bx * 32 + tx];
    }
    __syncthreads();
    const int m = by * 32 + tx;
    const int batch = m >> 11, srow = m & 2047;
    #pragma unroll
    for (int r = 0; r < 4; r++) {
        int n = bx * 32 + ty + r * 8;
        float v = ts[tx][ty + r * 8];
        __nv_bfloat16 h = __float2bfloat16(v);
        __nv_bfloat16 l = __float2bfloat16(v - __bfloat162float(h));
        size_t dst = ((size_t)batch * DVC + n) * (size_t)SS + srow;
        g_Vthi[dst] = h;
        g_Vtlo[dst] = l;
    }
}

// ---------------------------------------------------------------------------
// attn: tensor-core Shepard attention.
// Block = (batch, 64 q-rows); 256 threads / 8 warps; 64-key chunks.
// ---------------------------------------------------------------------------
#define QPITCH 272
#define KPITCH 272
#define VPITCH 144
#define WPITCH 144

#define OFF_QH 0
#define OFF_QL 17408
#define OFF_KH 34816
#define OFF_KL 52224
#define OFF_VH 69632
#define OFF_VL 106496
#define OFF_WH 143360
#define OFF_WL 152576
#define OFF_Q2 161792
#define OFF_K2 162048
#define OFF_WS 162304
#define ATT_SMEM_BYTES 162560

__device__ __forceinline__ void attn_load_k(uint32_t sKh, uint32_t sKl,
                                            int krow0c, int tid)
{
    #pragma unroll
    for (int i = 0; i < 4; i++) {
        int idx = tid + i * 256;
        int row = idx >> 4, seg = idx & 15;
        size_t src = (size_t)(krow0c + row) * DQKC + seg * 8;
        CPA16(sKh + row * KPITCH + seg * 16, g_Khi + src);
        CPA16(sKl + row * KPITCH + seg * 16, g_Klo + src);
    }
}

__device__ __forceinline__ void attn_load_v(uint32_t sVh, uint32_t sVl,
                                            int b, int kb, int tid)
{
    #pragma unroll
    for (int i = 0; i < 8; i++) {
        int idx = tid + i * 256;
        int n = idx >> 3, seg = idx & 7;
        size_t src = ((size_t)b * DVC + n) * (size_t)SS + kb * 64 + seg * 8;
        CPA16(sVh + n * VPITCH + seg * 16, g_Vthi + src);
        CPA16(sVl + n * VPITCH + seg * 16, g_Vtlo + src);
    }
}

__global__ __launch_bounds__(256) void attn_kernel()
{
    extern __shared__ char smc[];
    const uint32_t sb = smem_u32(smc);
    float* q2s  = (float*)(smc + OFF_Q2);
    float* k2s  = (float*)(smc + OFF_K2);
    float* wsum = (float*)(smc + OFF_WS);

    const int tid  = threadIdx.x;
    const int warp = tid >> 5, lane = tid & 31;
    const int lr = lane & 7, gq = lane >> 3;
    const int mrow = lane >> 2, ncol = (lane & 3) * 2;

    const int b  = blockIdx.x >> 5;
    const int qt = blockIdx.x & 31;
    const int qrow0 = b * SS + qt * 64;
    const int krow0 = b * SS;

    // Load Q tile (once) + chunk 0
    #pragma unroll
    for (int i = 0; i < 4; i++) {
        int idx = tid + i * 256;
        int row = idx >> 4, seg = idx & 15;
        size_t src = (size_t)(qrow0 + row) * DQKC + seg * 8;
        CPA16(sb + OFF_QH + row * QPITCH + seg * 16, g_Qhi + src);
        CPA16(sb + OFF_QL + row * QPITCH + seg * 16, g_Qlo + src);
    }
    attn_load_k(sb + OFF_KH, sb + OFF_KL, krow0, tid);
    attn_load_v(sb + OFF_VH, sb + OFF_VL, b, 0, tid);
    if (tid < 16) CPA16(sb + OFF_K2 + tid * 16, g_K2 + krow0 + tid * 4);
    CP_COMMIT();
    if (tid < 64) { wsum[tid] = 0.0f; q2s[tid] = g_Q2[qrow0 + tid]; }

    float acc[4][4][4] = {};

    const int wmA = (warp & 1) * 32;
    const int wnA = (warp >> 1) * 16;
    const int wnB = warp * 32;
    const uint32_t aQ = (lr + (gq & 1) * 8) * QPITCH + (gq >> 1) * 16;
    const uint32_t bK = (wnA + lr + (gq >> 1) * 8) * KPITCH + (gq & 1) * 16;
    const uint32_t aW = (lr + (gq & 1) * 8) * WPITCH + (gq >> 1) * 16;
    const uint32_t bV = (wnB + lr + (gq >> 1) * 8) * VPITCH + (gq & 1) * 16;

    for (int kc = 0; kc < 32; kc++) {
        CP_WAIT0();
        __syncthreads();

        // ---- Phase A: S = Q @ K^T (64 x 64, K=128), split-bf16 3-MMA ----
        float s[2][2][4] = {};
        #pragma unroll
        for (int ks = 0; ks < 8; ks++) {
            uint32_t ah[2][4], al[2][4], bh[4], bl[4];
            LDSM4(ah[0], sb + OFF_QH + aQ + (wmA +  0) * QPITCH + ks * 32);
            LDSM4(ah[1], sb + OFF_QH + aQ + (wmA + 16) * QPITCH + ks * 32);
            LDSM4(al[0], sb + OFF_QL + aQ + (wmA +  0) * QPITCH + ks * 32);
            LDSM4(al[1], sb + OFF_QL + aQ + (wmA + 16) * QPITCH + ks * 32);
            LDSM4(bh, sb + OFF_KH + bK + ks * 32);
            LDSM4(bl, sb + OFF_KL + bK + ks * 32);
            #pragma unroll
            for (int mf = 0; mf < 2; mf++) {
                #pragma unroll
                for (int nf = 0; nf < 2; nf++) {
                    MMA16816(s[mf][nf], ah[mf], bh[nf * 2], bh[nf * 2 + 1]);
                    MMA16816(s[mf][nf], ah[mf], bl[nf * 2], bl[nf * 2 + 1]);
                    MMA16816(s[mf][nf], al[mf], bh[nf * 2], bh[nf * 2 + 1]);
                }
            }
        }

        // ---- w = 1/max(d2, 1e-16); write split-bf16 to sW; row sums ----
        #pragma unroll
        for (int mf = 0; mf < 2; mf++) {
            int r0 = wmA + mf * 16 + mrow;
            int r1 = r0 + 8;
            float q20 = q2s[r0], q21 = q2s[r1];
            float rs0 = 0.0f, rs1 = 0.0f;
            #pragma unroll
            for (int nf = 0; nf < 2; nf++) {
                int n0 = wnA + nf * 8 + ncol;
                float k20 = k2s[n0], k21 = k2s[n0 + 1];
                float d00 = fmaxf(q20 + k20 - 2.0f * s[mf][nf][0], 0.0f);
                float d01 = fmaxf(q20 + k21 - 2.0f * s[mf][nf][1], 0.0f);
                float d10 = fmaxf(q21 + k20 - 2.0f * s[mf][nf][2], 0.0f);
                float d11 = fmaxf(q21 + k21 - 2.0f * s[mf][nf][3], 0.0f);
                float w00 = 1.0f / fmaxf(d00, 1e-16f);
                float w01 = 1.0f / fmaxf(d01, 1e-16f);
                float w10 = 1.0f / fmaxf(d10, 1e-16f);
                float w11 = 1.0f / fmaxf(d11, 1e-16f);
                uint32_t hw, lw;
                split2(w00, w01, hw, lw);
                *(uint32_t*)(smc + OFF_WH + r0 * WPITCH + n0 * 2) = hw;
                *(uint32_t*)(smc + OFF_WL + r0 * WPITCH + n0 * 2) = lw;
                split2(w10, w11, hw, lw);
                *(uint32_t*)(smc + OFF_WH + r1 * WPITCH + n0 * 2) = hw;
                *(uint32_t*)(smc + OFF_WL + r1 * WPITCH + n0 * 2) = lw;
                rs0 += w00 + w01;
                rs1 += w10 + w11;
            }
            atomicAdd(&wsum[r0], rs0);
            atomicAdd(&wsum[r1], rs1);
        }
        __syncthreads();

        // prefetch next K (+k2) — overlaps phase B
        if (kc + 1 < 32) {
            attn_load_k(sb + OFF_KH, sb + OFF_KL, krow0 + (kc + 1) * 64, tid);
            if (tid < 16) CPA16(sb + OFF_K2 + tid * 16,
                                g_K2 + krow0 + (kc + 1) * 64 + tid * 4);
            CP_COMMIT();
        }

        // ---- Phase B: acc += w @ V (64 x 256, K=64 keys) ----
        #pragma unroll
        for (int ks = 0; ks < 4; ks++) {
            uint32_t awh[4][4], awl[4][4], bvh[2][4], bvl[2][4];
            #pragma unroll
            for (int mf = 0; mf < 4; mf++) {
                LDSM4(awh[mf], sb + OFF_WH + aW + mf * 16 * WPITCH + ks * 32);
                LDSM4(awl[mf], sb + OFF_WL + aW + mf * 16 * WPITCH + ks * 32);
            }
            #pragma unroll
            for (int np = 0; np < 2; np++) {
                LDSM4(bvh[np], sb + OFF_VH + bV + np * 16 * VPITCH + ks * 32);
                LDSM4(bvl[np], sb + OFF_VL + bV + np * 16 * VPITCH + ks * 32);
            }
            #pragma unroll
            for (int mf = 0; mf < 4; mf++) {
                #pragma unroll
                for (int nf = 0; nf < 4; nf++) {
                    uint32_t b0h = bvh[nf >> 1][(nf & 1) * 2];
                    uint32_t b1h = bvh[nf >> 1][(nf & 1) * 2 + 1];
                    uint32_t b0l = bvl[nf >> 1][(nf & 1) * 2];
                    uint32_t b1l = bvl[nf >> 1][(nf & 1) * 2 + 1];
                    MMA16816(acc[mf][nf], awh[mf], b0h, b1h);
                    MMA16816(acc[mf][nf], awh[mf], b0l, b1l);
                    MMA16816(acc[mf][nf], awl[mf], b0h, b1h);
                }
            }
        }
        __syncthreads();

        if (kc + 1 < 32) {
            attn_load_v(sb + OFF_VH, sb + OFF_VL, b, kc + 1, tid);
            CP_COMMIT();
        }
    }

    // ---- Epilogue: normalize, gate with G, split-bf16 P for out_gemm ----
    #pragma unroll
    for (int mf = 0; mf < 4; mf++) {
        int lm0 = mf * 16 + mrow;
        float inv0 = 1.0f / wsum[lm0];
        float inv1 = 1.0f / wsum[lm0 + 8];
        size_t gm0 = (size_t)(qrow0 + lm0) * DVC;
        size_t gm1 = gm0 + 8 * DVC;
        #pragma unroll
        for (int nf = 0; nf < 4; nf++) {
            int n = wnB + nf * 8 + ncol;
            float2 gA = *(const float2*)&g_G[gm0 + n];
            float2 gB = *(const float2*)&g_G[gm1 + n];
            float p00 = acc[mf][nf][0] * inv0 * gA.x;
            float p01 = acc[mf][nf][1] * inv0 * gA.y;
            float p10 = acc[mf][nf][2] * inv1 * gB.x;
            float p11 = acc[mf][nf][3] * inv1 * gB.y;
            uint32_t hw, lw;
            split2(p00, p01, hw, lw);
            *(uint32_t*)&g_Phi[gm0 + n] = hw;
            *(uint32_t*)&g_Plo[gm0 + n] = lw;
            split2(p10, p11, hw, lw);
            *(uint32_t*)&g_Phi[gm1 + n] = hw;
            *(uint32_t*)&g_Plo[gm1 + n] = lw;
        }
    }
}

// ---------------------------------------------------------------------------
// out_gemm: out = X + P @ Wp + bp  (R4, unchanged)
// ---------------------------------------------------------------------------
__global__ __launch_bounds__(256) void out_gemm(
    const float* __restrict__ X, const float* __restrict__ bp,
    float* __restrict__ outp)
{
    extern __shared__ char smraw[];
    uint32_t sbase = smem_u32(smraw);
    const int tid = threadIdx.x;
    const int m0 = blockIdx.x * 128;
    const int n0 = blockIdx.y * 128;

    const __nv_bfloat16* Ahi = g_Phi + (size_t)m0 * DVC;
    const __nv_bfloat16* Alo = g_Plo + (size_t)m0 * DVC;
    const __nv_bfloat16* Bhi = g_Wpthi + (size_t)n0 * DVC;
    const __nv_bfloat16* Blo = g_Wptlo + (size_t)n0 * DVC;

    const int warp = tid >> 5, lane = tid & 31;
    const int lr = lane & 7, gq = lane >> 3;
    const int wm = (warp & 1) * 64, wn = (warp >> 1) * 32;
    const uint32_t a_off = (wm + lr + (gq & 1) * 8) * 80 + (gq >> 1) * 16;
    const uint32_t b_off = (wn + lr + (gq >> 1) * 8) * 80 + (gq & 1) * 16;

    float acc[4][4][4] = {};

    stage_copy(sbase, Ahi, Alo, DVC, Bhi, Blo, DVC, 0, tid);
    CP_COMMIT();
    for (int kb = 0; kb < 8; kb++) {
        if (kb + 1 < 8) {
            stage_copy(sbase + ((kb + 1) & 1) * STAGE_BYTES,
                       Ahi, Alo, DVC, Bhi, Blo, DVC, (kb + 1) * 32, tid);
            CP_COMMIT();
            CP_WAIT1();
        } else {
            CP_WAIT0();
        }
        __syncthreads();
        compute_stage(sbase + (kb & 1) * STAGE_BYTES, a_off, b_off, acc);
        __syncthreads();
    }

    const int mrow = lane >> 2, ncol = (lane & 3) * 2;
    #pragma unroll
    for (int mf = 0; mf < 4; mf++) {
        #pragma unroll
        for (int nf = 0; nf < 4; nf++) {
            int m = m0 + wm + mf * 16 + mrow;
            int n = n0 + wn + nf * 8 + ncol;
            float b0 = bp[n], b1 = bp[n + 1];
            float2 x0 = *(const float2*)&X[(size_t)m * DD + n];
            float2 x1 = *(const float2*)&X[(size_t)(m + 8) * DD + n];
            *(float2*)&outp[(size_t)m * DD + n] =
                make_float2(acc[mf][nf][0] + b0 + x0.x, acc[mf][nf][1] + b1 + x0.y);
            *(float2*)&outp[(size_t)(m + 8) * DD + n] =
                make_float2(acc[mf][nf][2] + b0 + x1.x, acc[mf][nf][3] + b1 + x1.y);
        }
    }
}

// ---------------------------------------------------------------------------
extern "C" void kernel_launch(void* const* d_in, const int* in_sizes, int n_in,
                              void* d_out, int out_size)
{
    const float* X  = (const float*)d_in[0];
    const float* Wq = (const float*)d_in[1];
    const float* bq = (const float*)d_in[2];
    const float* Wk = (const float*)d_in[3];
    const float* bk = (const float*)d_in[4];
    const float* Wv = (const float*)d_in[5];
    const float* bv = (const float*)d_in[6];
    const float* Wg = (const float*)d_in[7];
    const float* bg = (const float*)d_in[8];
    const float* Wp = (const float*)d_in[9];
    const float* bp = (const float*)d_in[10];
    float* out = (float*)d_out;

    cudaFuncSetAttribute(proj_gemm, cudaFuncAttributeMaxDynamicSharedMemorySize, GEMM_SMEM_BYTES);
    cudaFuncSetAttribute(out_gemm,  cudaFuncAttributeMaxDynamicSharedMemorySize, GEMM_SMEM_BYTES);
    cudaFuncSetAttribute(attn_kernel, cudaFuncAttributeMaxDynamicSharedMemorySize, ATT_SMEM_BYTES);

    split_x_kernel<<<MM * DD / 1024, 256>>>(X);
    split_w_kernel<<<(NPROJ * DD + DD * DVC) / 256, 256>>>(Wq, Wk, Wv, Wg, Wp);
    proj_gemm<<<dim3(64, 6), 256, GEMM_SMEM_BYTES>>>(bq, bk, bv, bg);
    sumsq_kernel<<<64, 256>>>();
    vtrans_kernel<<<dim3(8, 256), 256>>>();
    attn_kernel<<<128, 256, ATT_SMEM_BYTES>>>();
    out_gemm<<<dim3(64, 8), 256, GEMM_SMEM_BYTES>>>(X, bp, out);
}

// round 6
// speedup vs baseline: 3.4387x; 1.3903x over previous
#include <cuda_runtime.h>
#include <cuda_fp16.h>
#include <cstdint>

#define BB   4
#define SS   2048
#define DD   1024
#define DQKC 128
#define DVC  256
#define MM   (BB * SS)   // 8192
#define NPROJ 768

// ---------------------------------------------------------------------------
// Device scratch
// ---------------------------------------------------------------------------
__device__ __align__(256) __half g_Xhi[MM * DD];
__device__ __align__(256) __half g_Xlo[MM * DD];
__device__ __align__(256) __half g_Wt[NPROJ * DD];      // single fp16 (B side)
__device__ __align__(256) __half g_Wpt[DD * DVC];       // single fp16
__device__ __align__(256) __half g_Qhi[MM * DQKC];
__device__ __align__(256) __half g_Qlo[MM * DQKC];
__device__ __align__(256) __half g_Khi[MM * DQKC];      // single fp16 (B side)
__device__ __align__(256) __half g_Vt[BB * DVC * SS];   // [b][n][s] single fp16
__device__ __align__(256) __half g_Phi[MM * DVC];       // (AV*G) hi
__device__ __align__(256) __half g_Plo[MM * DVC];
__device__ __align__(256) float g_V[MM * DVC];
__device__ __align__(256) float g_G[MM * DVC];
__device__ __align__(256) float g_Q2[MM];
__device__ __align__(256) float g_K2[MM];

// ---------------------------------------------------------------------------
// PTX helpers (baseline ISA: mma.sync / ldmatrix / cp.async)
// ---------------------------------------------------------------------------
__device__ __forceinline__ uint32_t smem_u32(const void* p) {
    uint32_t a;
    asm("{ .reg .u64 t; cvta.to.shared.u64 t, %1; cvt.u32.u64 %0, t; }"
        : "=r"(a) : "l"(p));
    return a;
}

#define LDSM4(r, addr) \
    asm volatile("ldmatrix.sync.aligned.m8n8.x4.shared.b16 {%0,%1,%2,%3}, [%4];" \
        : "=r"((r)[0]), "=r"((r)[1]), "=r"((r)[2]), "=r"((r)[3]) : "r"(addr))

#define MMA16816(c, a, b0, b1) \
    asm volatile("mma.sync.aligned.m16n8k16.row.col.f32.f16.f16.f32 " \
        "{%0,%1,%2,%3}, {%4,%5,%6,%7}, {%8,%9}, {%0,%1,%2,%3};" \
        : "+f"((c)[0]), "+f"((c)[1]), "+f"((c)[2]), "+f"((c)[3]) \
        : "r"((a)[0]), "r"((a)[1]), "r"((a)[2]), "r"((a)[3]), "r"(b0), "r"(b1))

#define CPA16(s, g) \
    asm volatile("cp.async.ca.shared.global [%0], [%1], 16;" :: "r"(s), "l"(g) : "memory")
#define CP_COMMIT() asm volatile("cp.async.commit_group;" ::: "memory")
#define CP_WAIT1()  asm volatile("cp.async.wait_group 1;" ::: "memory")
#define CP_WAIT0()  asm volatile("cp.async.wait_group 0;" ::: "memory")

__device__ __forceinline__ void split2h(float a, float b, uint32_t& hw, uint32_t& lw) {
    __half ha = __float2half_rn(a), hb = __float2half_rn(b);
    __half la = __float2half_rn(a - __half2float(ha));
    __half lb = __float2half_rn(b - __half2float(hb));
    __half2 hp(ha, hb), lp(la, lb);
    hw = *reinterpret_cast<uint32_t*>(&hp);
    lw = *reinterpret_cast<uint32_t*>(&lp);
}
__device__ __forceinline__ uint32_t pack2h(float a, float b) {
    __half2 hp(__float2half_rn(a), __float2half_rn(b));
    return *reinterpret_cast<uint32_t*>(&hp);
}

// ---------------------------------------------------------------------------
// Prep: split X fp32 -> fp16 hi/lo; weights -> single fp16 transposed
// ---------------------------------------------------------------------------
__global__ __launch_bounds__(256) void split_x_kernel(const float* __restrict__ X)
{
    int i = (blockIdx.x * 256 + threadIdx.x) * 4;
    float4 v = *(const float4*)&X[i];
    uint32_t hw0, lw0, hw1, lw1;
    split2h(v.x, v.y, hw0, lw0);
    split2h(v.z, v.w, hw1, lw1);
    *(uint2*)&g_Xhi[i] = make_uint2(hw0, hw1);
    *(uint2*)&g_Xlo[i] = make_uint2(lw0, lw1);
}

__global__ __launch_bounds__(256) void split_w_kernel(
    const float* __restrict__ Wq, const float* __restrict__ Wk,
    const float* __restrict__ Wv, const float* __restrict__ Wg,
    const float* __restrict__ Wp)
{
    int idx = blockIdx.x * 256 + threadIdx.x;
    if (idx < NPROJ * DD) {
        int n = idx >> 10, k = idx & 1023;
        const float* W; int col; int ncols;
        if (n < 128)      { W = Wq; col = n;       ncols = 128; }
        else if (n < 256) { W = Wk; col = n - 128; ncols = 128; }
        else if (n < 512) { W = Wv; col = n - 256; ncols = 256; }
        else              { W = Wg; col = n - 512; ncols = 256; }
        g_Wt[idx] = __float2half_rn(W[k * ncols + col]);
    } else {
        int j = idx - NPROJ * DD;
        int n = j >> 8, k = j & 255;
        g_Wpt[j] = __float2half_rn(Wp[k * DD + n]);
    }
}

// ---------------------------------------------------------------------------
// GEMM machinery: A split (hi/lo), B single. 3 tiles per stage, 2-MMA.
// ---------------------------------------------------------------------------
#define TILE_BYTES   10240           // 128 rows * 80B (32 fp16 + pad)
#define STAGE_BYTES  (3 * TILE_BYTES)
#define GEMM_SMEM_BYTES (2 * STAGE_BYTES)   // 61440

__device__ __forceinline__ void stage_copy(
    uint32_t sstage,
    const __half* __restrict__ Ahi, const __half* __restrict__ Alo, int lda,
    const __half* __restrict__ B, int ldb, int k0, int tid)
{
    #pragma unroll
    for (int i = 0; i < 2; i++) {
        int c = tid + i * 256;
        int row = c >> 2;
        int seg = c & 3;
        uint32_t so = row * 80 + seg * 16;
        size_t ga = (size_t)row * lda + k0 + seg * 8;
        size_t gb = (size_t)row * ldb + k0 + seg * 8;
        CPA16(sstage +                  so, Ahi + ga);
        CPA16(sstage +      TILE_BYTES + so, Alo + ga);
        CPA16(sstage + 2 * TILE_BYTES + so, B   + gb);
    }
}

__device__ __forceinline__ void compute_stage(
    uint32_t sstage, uint32_t a_off, uint32_t b_off, float acc[4][4][4])
{
    #pragma unroll
    for (int ks = 0; ks < 2; ks++) {
        uint32_t ah[4][4], al[4][4], bh[2][4];
        #pragma unroll
        for (int mf = 0; mf < 4; mf++) {
            LDSM4(ah[mf], sstage +              a_off + mf * 1280 + ks * 32);
            LDSM4(al[mf], sstage + TILE_BYTES + a_off + mf * 1280 + ks * 32);
        }
        #pragma unroll
        for (int np = 0; np < 2; np++)
            LDSM4(bh[np], sstage + 2 * TILE_BYTES + b_off + np * 1280 + ks * 32);
        #pragma unroll
        for (int mf = 0; mf < 4; mf++) {
            #pragma unroll
            for (int nf = 0; nf < 4; nf++) {
                uint32_t b0 = bh[nf >> 1][(nf & 1) * 2], b1 = bh[nf >> 1][(nf & 1) * 2 + 1];
                MMA16816(acc[mf][nf], ah[mf], b0, b1);
                MMA16816(acc[mf][nf], al[mf], b0, b1);
            }
        }
    }
}

// ---------------------------------------------------------------------------
// proj_gemm: grid (64, 6). slabs: 0=Q(split fp16) 1=K(single fp16)
//            2=V[:128] 3=V[128:] 4=G[:128] 5=G[128:]  (fp32)
// ---------------------------------------------------------------------------
__global__ __launch_bounds__(256) void proj_gemm(
    const float* __restrict__ bq, const float* __restrict__ bk,
    const float* __restrict__ bv, const float* __restrict__ bg)
{
    extern __shared__ char smraw[];
    uint32_t sbase = smem_u32(smraw);
    const int tid = threadIdx.x;
    const int m0 = blockIdx.x * 128;
    const int slab = blockIdx.y;
    const int nbase = slab * 128;

    const __half* Ahi = g_Xhi + (size_t)m0 * DD;
    const __half* Alo = g_Xlo + (size_t)m0 * DD;
    const __half* B   = g_Wt + (size_t)nbase * DD;

    const int warp = tid >> 5, lane = tid & 31;
    const int lr = lane & 7, gq = lane >> 3;
    const int wm = (warp & 1) * 64, wn = (warp >> 1) * 32;
    const uint32_t a_off = (wm + lr + (gq & 1) * 8) * 80 + (gq >> 1) * 16;
    const uint32_t b_off = (wn + lr + (gq >> 1) * 8) * 80 + (gq & 1) * 16;

    float acc[4][4][4] = {};

    stage_copy(sbase, Ahi, Alo, DD, B, DD, 0, tid);
    CP_COMMIT();
    for (int kb = 0; kb < 32; kb++) {
        if (kb + 1 < 32) {
            stage_copy(sbase + ((kb + 1) & 1) * STAGE_BYTES,
                       Ahi, Alo, DD, B, DD, (kb + 1) * 32, tid);
            CP_COMMIT();
            CP_WAIT1();
        } else {
            CP_WAIT0();
        }
        __syncthreads();
        compute_stage(sbase + (kb & 1) * STAGE_BYTES, a_off, b_off, acc);
        __syncthreads();
    }

    const int mrow = lane >> 2, ncol = (lane & 3) * 2;
    const float* bias;
    switch (slab) {
        case 0:  bias = bq; break;
        case 1:  bias = bk; break;
        case 2: case 3: bias = bv; break;
        default: bias = bg; break;
    }
    const int nb_off = (slab == 3 || slab == 5) ? 128 : 0;

    #pragma unroll
    for (int mf = 0; mf < 4; mf++) {
        #pragma unroll
        for (int nf = 0; nf < 4; nf++) {
            int m = m0 + wm + mf * 16 + mrow;
            int n = nb_off + wn + nf * 8 + ncol;
            float b0 = bias[n], b1 = bias[n + 1];
            float v00 = acc[mf][nf][0] + b0, v01 = acc[mf][nf][1] + b1;
            float v10 = acc[mf][nf][2] + b0, v11 = acc[mf][nf][3] + b1;
            if (slab == 0) {
                uint32_t hw, lw;
                split2h(v00, v01, hw, lw);
                *(uint32_t*)&g_Qhi[(size_t)m * DQKC + n] = hw;
                *(uint32_t*)&g_Qlo[(size_t)m * DQKC + n] = lw;
                split2h(v10, v11, hw, lw);
                *(uint32_t*)&g_Qhi[(size_t)(m + 8) * DQKC + n] = hw;
                *(uint32_t*)&g_Qlo[(size_t)(m + 8) * DQKC + n] = lw;
            } else if (slab == 1) {
                *(uint32_t*)&g_Khi[(size_t)m * DQKC + n] = pack2h(v00, v01);
                *(uint32_t*)&g_Khi[(size_t)(m + 8) * DQKC + n] = pack2h(v10, v11);
            } else {
                float* outp = (slab < 4) ? g_V : g_G;
                *(float2*)&outp[(size_t)m * DVC + n] = make_float2(v00, v01);
                *(float2*)&outp[(size_t)(m + 8) * DVC + n] = make_float2(v10, v11);
            }
        }
    }
}

// ---------------------------------------------------------------------------
// sumsq: q2 from Qhi+Qlo, k2 from Khi (the effective values used in the MMA)
// ---------------------------------------------------------------------------
__global__ __launch_bounds__(256) void sumsq_kernel()
{
    int r = blockIdx.x * 256 + threadIdx.x;
    float s = 0.0f;
    if (r < MM) {
        const __half2* hs = (const __half2*)&g_Qhi[(size_t)r * DQKC];
        const __half2* ls = (const __half2*)&g_Qlo[(size_t)r * DQKC];
        #pragma unroll
        for (int k = 0; k < 64; k++) {
            float2 h = __half22float2(hs[k]);
            float2 l = __half22float2(ls[k]);
            float a = h.x + l.x, b = h.y + l.y;
            s = fmaf(a, a, s); s = fmaf(b, b, s);
        }
        g_Q2[r] = s;
    } else {
        const __half2* hs = (const __half2*)&g_Khi[(size_t)(r - MM) * DQKC];
        #pragma unroll
        for (int k = 0; k < 64; k++) {
            float2 h = __half22float2(hs[k]);
            s = fmaf(h.x, h.x, s); s = fmaf(h.y, h.y, s);
        }
        g_K2[r - MM] = s;
    }
}

// ---------------------------------------------------------------------------
// vtrans: V[8192][256] fp32 -> Vt[b][n][s] single fp16
// ---------------------------------------------------------------------------
__global__ __launch_bounds__(256) void vtrans_kernel()
{
    __shared__ float ts[32][33];
    const int bx = blockIdx.x;   // n tile 0..7
    const int by = blockIdx.y;   // m tile 0..255
    const int tx = threadIdx.x & 31, ty = threadIdx.x >> 5;
    #pragma unroll
    for (int r = 0; r < 4; r++) {
        int m = by * 32 + ty + r * 8;
        ts[ty + r * 8][tx] = g_V[(size_t)m * DVC + bx * 32 + tx];
    }
    __syncthreads();
    const int m = by * 32 + tx;
    const int batch = m >> 11, srow = m & 2047;
    #pragma unroll
    for (int r = 0; r < 4; r++) {
        int n = bx * 32 + ty + r * 8;
        g_Vt[((size_t)batch * DVC + n) * (size_t)SS + srow] =
            __float2half_rn(ts[tx][ty + r * 8]);
    }
}

// ---------------------------------------------------------------------------
// attn: tensor-core Shepard attention, fp16 2-MMA, double-buffered K/V.
// Block = (batch, 64 q-rows); 256 threads / 8 warps; 64-key chunks.
// ---------------------------------------------------------------------------
#define QPITCH 272
#define KPITCH 272
#define VPITCH 144
#define WPITCH 144

#define OFF_QH  0
#define OFF_QL  17408
#define OFF_KH0 34816
#define OFF_KH1 52224
#define OFF_VH0 69632
#define OFF_VH1 106496
#define OFF_WH  143360
#define OFF_WL  152576
#define OFF_Q2  161792
#define OFF_K20 162048
#define OFF_K21 162304
#define OFF_WS  162560
#define ATT_SMEM_BYTES 162816

#define WSCALE 1024.0f

__device__ __forceinline__ void attn_load_k(uint32_t sKh, int krow0c, int tid)
{
    #pragma unroll
    for (int i = 0; i < 4; i++) {
        int idx = tid + i * 256;
        int row = idx >> 4, seg = idx & 15;
        CPA16(sKh + row * KPITCH + seg * 16,
              g_Khi + (size_t)(krow0c + row) * DQKC + seg * 8);
    }
}

__device__ __forceinline__ void attn_load_v(uint32_t sVh, int b, int kb, int tid)
{
    #pragma unroll
    for (int i = 0; i < 8; i++) {
        int idx = tid + i * 256;
        int n = idx >> 3, seg = idx & 7;
        CPA16(sVh + n * VPITCH + seg * 16,
              g_Vt + ((size_t)b * DVC + n) * (size_t)SS + kb * 64 + seg * 8);
    }
}

__global__ __launch_bounds__(256) void attn_kernel()
{
    extern __shared__ char smc[];
    const uint32_t sb = smem_u32(smc);
    float* q2s  = (float*)(smc + OFF_Q2);
    float* wsum = (float*)(smc + OFF_WS);

    const int tid  = threadIdx.x;
    const int warp = tid >> 5, lane = tid & 31;
    const int lr = lane & 7, gq = lane >> 3;
    const int mrow = lane >> 2, ncol = (lane & 3) * 2;

    const int b  = blockIdx.x >> 5;
    const int qt = blockIdx.x & 31;
    const int qrow0 = b * SS + qt * 64;
    const int krow0 = b * SS;

    // Q (split) + chunk 0 (group 0), chunk 1 (group 1)
    #pragma unroll
    for (int i = 0; i < 4; i++) {
        int idx = tid + i * 256;
        int row = idx >> 4, seg = idx & 15;
        size_t src = (size_t)(qrow0 + row) * DQKC + seg * 8;
        CPA16(sb + OFF_QH + row * QPITCH + seg * 16, g_Qhi + src);
        CPA16(sb + OFF_QL + row * QPITCH + seg * 16, g_Qlo + src);
    }
    attn_load_k(sb + OFF_KH0, krow0, tid);
    attn_load_v(sb + OFF_VH0, b, 0, tid);
    if (tid < 16) CPA16(sb + OFF_K20 + tid * 16, g_K2 + krow0 + tid * 4);
    CP_COMMIT();
    attn_load_k(sb + OFF_KH1, krow0 + 64, tid);
    attn_load_v(sb + OFF_VH1, b, 1, tid);
    if (tid < 16) CPA16(sb + OFF_K21 + tid * 16, g_K2 + krow0 + 64 + tid * 4);
    CP_COMMIT();
    if (tid < 64) { wsum[tid] = 0.0f; q2s[tid] = g_Q2[qrow0 + tid]; }

    float acc[4][4][4] = {};

    const int wmA = (warp & 1) * 32;
    const int wnA = (warp >> 1) * 16;
    const int wnB = warp * 32;
    const uint32_t aQ = (lr + (gq & 1) * 8) * QPITCH + (gq >> 1) * 16;
    const uint32_t bK = (wnA + lr + (gq >> 1) * 8) * KPITCH + (gq & 1) * 16;
    const uint32_t aW = (lr + (gq & 1) * 8) * WPITCH + (gq >> 1) * 16;
    const uint32_t bV = (wnB + lr + (gq >> 1) * 8) * VPITCH + (gq & 1) * 16;

    for (int kc = 0; kc < 32; kc++) {
        if (kc < 31) CP_WAIT1(); else CP_WAIT0();
        __syncthreads();

        const uint32_t sKH = sb + ((kc & 1) ? OFF_KH1 : OFF_KH0);
        const uint32_t sVH = sb + ((kc & 1) ? OFF_VH1 : OFF_VH0);
        const float* k2s = (const float*)(smc + ((kc & 1) ? OFF_K21 : OFF_K20));

        // ---- Phase A: S = Q @ K^T (64x64, K=128), 2-MMA fp16 ----
        float s[2][2][4] = {};
        #pragma unroll
        for (int ks = 0; ks < 8; ks++) {
            uint32_t ah[2][4], al[2][4], bh[4];
            LDSM4(ah[0], sb + OFF_QH + aQ + (wmA +  0) * QPITCH + ks * 32);
            LDSM4(ah[1], sb + OFF_QH + aQ + (wmA + 16) * QPITCH + ks * 32);
            LDSM4(al[0], sb + OFF_QL + aQ + (wmA +  0) * QPITCH + ks * 32);
            LDSM4(al[1], sb + OFF_QL + aQ + (wmA + 16) * QPITCH + ks * 32);
            LDSM4(bh, sKH + bK + ks * 32);
            #pragma unroll
            for (int mf = 0; mf < 2; mf++) {
                #pragma unroll
                for (int nf = 0; nf < 2; nf++) {
                    MMA16816(s[mf][nf], ah[mf], bh[nf * 2], bh[nf * 2 + 1]);
                    MMA16816(s[mf][nf], al[mf], bh[nf * 2], bh[nf * 2 + 1]);
                }
            }
        }

        // ---- w = WSCALE/max(d2,1e-16); split-fp16 into sW; row sums ----
        #pragma unroll
        for (int mf = 0; mf < 2; mf++) {
            int r0 = wmA + mf * 16 + mrow;
            int r1 = r0 + 8;
            float q20 = q2s[r0], q21 = q2s[r1];
            float rs0 = 0.0f, rs1 = 0.0f;
            #pragma unroll
            for (int nf = 0; nf < 2; nf++) {
                int n0 = wnA + nf * 8 + ncol;
                float k20 = k2s[n0], k21 = k2s[n0 + 1];
                float d00 = fmaxf(q20 + k20 - 2.0f * s[mf][nf][0], 0.0f);
                float d01 = fmaxf(q20 + k21 - 2.0f * s[mf][nf][1], 0.0f);
                float d10 = fmaxf(q21 + k20 - 2.0f * s[mf][nf][2], 0.0f);
                float d11 = fmaxf(q21 + k21 - 2.0f * s[mf][nf][3], 0.0f);
                float w00 = WSCALE / fmaxf(d00, 1e-16f);
                float w01 = WSCALE / fmaxf(d01, 1e-16f);
                float w10 = WSCALE / fmaxf(d10, 1e-16f);
                float w11 = WSCALE / fmaxf(d11, 1e-16f);
                uint32_t hw, lw;
                split2h(w00, w01, hw, lw);
                *(uint32_t*)(smc + OFF_WH + r0 * WPITCH + n0 * 2) = hw;
                *(uint32_t*)(smc + OFF_WL + r0 * WPITCH + n0 * 2) = lw;
                split2h(w10, w11, hw, lw);
                *(uint32_t*)(smc + OFF_WH + r1 * WPITCH + n0 * 2) = hw;
                *(uint32_t*)(smc + OFF_WL + r1 * WPITCH + n0 * 2) = lw;
                rs0 += w00 + w01;
                rs1 += w10 + w11;
            }
            atomicAdd(&wsum[r0], rs0);
            atomicAdd(&wsum[r1], rs1);
        }
        __syncthreads();

        // ---- Phase B: acc += w @ V (64x256, K=64 keys), 2-MMA ----
        #pragma unroll
        for (int ks = 0; ks < 4; ks++) {
            uint32_t awh[4][4], awl[4][4], bvh[2][4];
            #pragma unroll
            for (int mf = 0; mf < 4; mf++) {
                LDSM4(awh[mf], sb + OFF_WH + aW + mf * 16 * WPITCH + ks * 32);
                LDSM4(awl[mf], sb + OFF_WL + aW + mf * 16 * WPITCH + ks * 32);
            }
            #pragma unroll
            for (int np = 0; np < 2; np++)
                LDSM4(bvh[np], sVH + bV + np * 16 * VPITCH + ks * 32);
            #pragma unroll
            for (int mf = 0; mf < 4; mf++) {
                #pragma unroll
                for (int nf = 0; nf < 4; nf++) {
                    uint32_t b0 = bvh[nf >> 1][(nf & 1) * 2];
                    uint32_t b1 = bvh[nf >> 1][(nf & 1) * 2 + 1];
                    MMA16816(acc[mf][nf], awh[mf], b0, b1);
                    MMA16816(acc[mf][nf], awl[mf], b0, b1);
                }
            }
        }
        __syncthreads();

        // prefetch chunk kc+2 into the buffers just freed
        if (kc + 2 < 32) {
            uint32_t dKH = sb + ((kc & 1) ? OFF_KH1 : OFF_KH0);
            uint32_t dVH = sb + ((kc & 1) ? OFF_VH1 : OFF_VH0);
            uint32_t dK2 = sb + ((kc & 1) ? OFF_K21 : OFF_K20);
            attn_load_k(dKH, krow0 + (kc + 2) * 64, tid);
            attn_load_v(dVH, b, kc + 2, tid);
            if (tid < 16) CPA16(dK2 + tid * 16, g_K2 + krow0 + (kc + 2) * 64 + tid * 4);
            CP_COMMIT();
        }
    }

    // ---- Epilogue: normalize (scale cancels), gate with G, split P ----
    #pragma unroll
    for (int mf = 0; mf < 4; mf++) {
        int lm0 = mf * 16 + mrow;
        float inv0 = 1.0f / wsum[lm0];
        float inv1 = 1.0f / wsum[lm0 + 8];
        size_t gm0 = (size_t)(qrow0 + lm0) * DVC;
        size_t gm1 = gm0 + 8 * DVC;
        #pragma unroll
        for (int nf = 0; nf < 4; nf++) {
            int n = wnB + nf * 8 + ncol;
            float2 gA = *(const float2*)&g_G[gm0 + n];
            float2 gB = *(const float2*)&g_G[gm1 + n];
            float p00 = acc[mf][nf][0] * inv0 * gA.x;
            float p01 = acc[mf][nf][1] * inv0 * gA.y;
            float p10 = acc[mf][nf][2] * inv1 * gB.x;
            float p11 = acc[mf][nf][3] * inv1 * gB.y;
            uint32_t hw, lw;
            split2h(p00, p01, hw, lw);
            *(uint32_t*)&g_Phi[gm0 + n] = hw;
            *(uint32_t*)&g_Plo[gm0 + n] = lw;
            split2h(p10, p11, hw, lw);
            *(uint32_t*)&g_Phi[gm1 + n] = hw;
            *(uint32_t*)&g_Plo[gm1 + n] = lw;
        }
    }
}

// ---------------------------------------------------------------------------
// out_gemm: out = X + P @ Wp + bp   (A = P split, B = Wpt single)
// ---------------------------------------------------------------------------
__global__ __launch_bounds__(256) void out_gemm(
    const float* __restrict__ X, const float* __restrict__ bp,
    float* __restrict__ outp)
{
    extern __shared__ char smraw[];
    uint32_t sbase = smem_u32(smraw);
    const int tid = threadIdx.x;
    const int m0 = blockIdx.x * 128;
    const int n0 = blockIdx.y * 128;

    const __half* Ahi = g_Phi + (size_t)m0 * DVC;
    const __half* Alo = g_Plo + (size_t)m0 * DVC;
    const __half* B   = g_Wpt + (size_t)n0 * DVC;

    const int warp = tid >> 5, lane = tid & 31;
    const int lr = lane & 7, gq = lane >> 3;
    const int wm = (warp & 1) * 64, wn = (warp >> 1) * 32;
    const uint32_t a_off = (wm + lr + (gq & 1) * 8) * 80 + (gq >> 1) * 16;
    const uint32_t b_off = (wn + lr + (gq >> 1) * 8) * 80 + (gq & 1) * 16;

    float acc[4][4][4] = {};

    stage_copy(sbase, Ahi, Alo, DVC, B, DVC, 0, tid);
    CP_COMMIT();
    for (int kb = 0; kb < 8; kb++) {
        if (kb + 1 < 8) {
            stage_copy(sbase + ((kb + 1) & 1) * STAGE_BYTES,
                       Ahi, Alo, DVC, B, DVC, (kb + 1) * 32, tid);
            CP_COMMIT();
            CP_WAIT1();
        } else {
            CP_WAIT0();
        }
        __syncthreads();
        compute_stage(sbase + (kb & 1) * STAGE_BYTES, a_off, b_off, acc);
        __syncthreads();
    }

    const int mrow = lane >> 2, ncol = (lane & 3) * 2;
    #pragma unroll
    for (int mf = 0; mf < 4; mf++) {
        #pragma unroll
        for (int nf = 0; nf < 4; nf++) {
            int m = m0 + wm + mf * 16 + mrow;
            int n = n0 + wn + nf * 8 + ncol;
            float b0 = bp[n], b1 = bp[n + 1];
            float2 x0 = *(const float2*)&X[(size_t)m * DD + n];
            float2 x1 = *(const float2*)&X[(size_t)(m + 8) * DD + n];
            *(float2*)&outp[(size_t)m * DD + n] =
                make_float2(acc[mf][nf][0] + b0 + x0.x, acc[mf][nf][1] + b1 + x0.y);
            *(float2*)&outp[(size_t)(m + 8) * DD + n] =
                make_float2(acc[mf][nf][2] + b0 + x1.x, acc[mf][nf][3] + b1 + x1.y);
        }
    }
}

// ---------------------------------------------------------------------------
extern "C" void kernel_launch(void* const* d_in, const int* in_sizes, int n_in,
                              void* d_out, int out_size)
{
    const float* X  = (const float*)d_in[0];
    const float* Wq = (const float*)d_in[1];
    const float* bq = (const float*)d_in[2];
    const float* Wk = (const float*)d_in[3];
    const float* bk = (const float*)d_in[4];
    const float* Wv = (const float*)d_in[5];
    const float* bv = (const float*)d_in[6];
    const float* Wg = (const float*)d_in[7];
    const float* bg = (const float*)d_in[8];
    const float* Wp = (const float*)d_in[9];
    const float* bp = (const float*)d_in[10];
    float* out = (float*)d_out;

    cudaFuncSetAttribute(proj_gemm, cudaFuncAttributeMaxDynamicSharedMemorySize, GEMM_SMEM_BYTES);
    cudaFuncSetAttribute(out_gemm,  cudaFuncAttributeMaxDynamicSharedMemorySize, GEMM_SMEM_BYTES);
    cudaFuncSetAttribute(attn_kernel, cudaFuncAttributeMaxDynamicSharedMemorySize, ATT_SMEM_BYTES);

    split_x_kernel<<<MM * DD / 1024, 256>>>(X);
    split_w_kernel<<<(NPROJ * DD + DD * DVC) / 256, 256>>>(Wq, Wk, Wv, Wg, Wp);
    proj_gemm<<<dim3(64, 6), 256, GEMM_SMEM_BYTES>>>(bq, bk, bv, bg);
    sumsq_kernel<<<64, 256>>>();
    vtrans_kernel<<<dim3(8, 256), 256>>>();
    attn_kernel<<<128, 256, ATT_SMEM_BYTES>>>();
    out_gemm<<<dim3(64, 8), 256, GEMM_SMEM_BYTES>>>(X, bp, out);
}

// round 7
// speedup vs baseline: 4.3033x; 1.2514x over previous
#include <cuda_runtime.h>
#include <cuda_fp16.h>
#include <cstdint>

#define BB   4
#define SS   2048
#define DD   1024
#define DQKC 128
#define DVC  256
#define MM   (BB * SS)   // 8192
#define NPROJ 768

// ---------------------------------------------------------------------------
// Device scratch (all operands single fp16)
// ---------------------------------------------------------------------------
__device__ __align__(256) __half g_Xh[MM * DD];
__device__ __align__(256) __half g_Wt[NPROJ * DD];      // [n][k]
__device__ __align__(256) __half g_Wpt[DD * DVC];       // [n][k]
__device__ __align__(256) __half g_Qh[MM * DQKC];
__device__ __align__(256) __half g_Kh[MM * DQKC];
__device__ __align__(256) __half g_Vt[BB * DVC * SS];   // [b][n][s]
__device__ __align__(256) __half g_Ph[MM * DVC];        // (AV*G)
__device__ __align__(256) float g_V[MM * DVC];
__device__ __align__(256) float g_G[MM * DVC];
__device__ __align__(256) float g_Q2[MM];
__device__ __align__(256) float g_K2[MM];

// ---------------------------------------------------------------------------
// PTX helpers
// ---------------------------------------------------------------------------
__device__ __forceinline__ uint32_t smem_u32(const void* p) {
    uint32_t a;
    asm("{ .reg .u64 t; cvta.to.shared.u64 t, %1; cvt.u32.u64 %0, t; }"
        : "=r"(a) : "l"(p));
    return a;
}

#define LDSM4(r, addr) \
    asm volatile("ldmatrix.sync.aligned.m8n8.x4.shared.b16 {%0,%1,%2,%3}, [%4];" \
        : "=r"((r)[0]), "=r"((r)[1]), "=r"((r)[2]), "=r"((r)[3]) : "r"(addr))

#define MMA16816(c, a, b0, b1) \
    asm volatile("mma.sync.aligned.m16n8k16.row.col.f32.f16.f16.f32 " \
        "{%0,%1,%2,%3}, {%4,%5,%6,%7}, {%8,%9}, {%0,%1,%2,%3};" \
        : "+f"((c)[0]), "+f"((c)[1]), "+f"((c)[2]), "+f"((c)[3]) \
        : "r"((a)[0]), "r"((a)[1]), "r"((a)[2]), "r"((a)[3]), "r"(b0), "r"(b1))

#define CPA16(s, g) \
    asm volatile("cp.async.ca.shared.global [%0], [%1], 16;" :: "r"(s), "l"(g) : "memory")
#define CP_COMMIT() asm volatile("cp.async.commit_group;" ::: "memory")
#define CP_WAIT1()  asm volatile("cp.async.wait_group 1;" ::: "memory")
#define CP_WAIT0()  asm volatile("cp.async.wait_group 0;" ::: "memory")

__device__ __forceinline__ uint32_t pack2h(float a, float b) {
    __half2 hp(__float2half_rn(a), __float2half_rn(b));
    return *reinterpret_cast<uint32_t*>(&hp);
}

// ---------------------------------------------------------------------------
// Prep
// ---------------------------------------------------------------------------
__global__ __launch_bounds__(256) void split_x_kernel(const float* __restrict__ X)
{
    int i = (blockIdx.x * 256 + threadIdx.x) * 4;
    float4 v = *(const float4*)&X[i];
    *(uint2*)&g_Xh[i] = make_uint2(pack2h(v.x, v.y), pack2h(v.z, v.w));
}

__global__ __launch_bounds__(256) void split_w_kernel(
    const float* __restrict__ Wq, const float* __restrict__ Wk,
    const float* __restrict__ Wv, const float* __restrict__ Wg,
    const float* __restrict__ Wp)
{
    int idx = blockIdx.x * 256 + threadIdx.x;
    if (idx < NPROJ * DD) {
        int n = idx >> 10, k = idx & 1023;
        const float* W; int col; int ncols;
        if (n < 128)      { W = Wq; col = n;       ncols = 128; }
        else if (n < 256) { W = Wk; col = n - 128; ncols = 128; }
        else if (n < 512) { W = Wv; col = n - 256; ncols = 256; }
        else              { W = Wg; col = n - 512; ncols = 256; }
        g_Wt[idx] = __float2half_rn(W[k * ncols + col]);
    } else {
        int j = idx - NPROJ * DD;
        int n = j >> 8, k = j & 255;
        g_Wpt[j] = __float2half_rn(Wp[k * DD + n]);
    }
}

// ---------------------------------------------------------------------------
// GEMM machinery: single fp16, 1 MMA. 2 tiles per stage.
// ---------------------------------------------------------------------------
#define TILE_BYTES   10240           // 128 rows * 80B (32 fp16 + pad)
#define STAGE_BYTES  (2 * TILE_BYTES)
#define GEMM_SMEM_BYTES (2 * STAGE_BYTES)   // 40960

__device__ __forceinline__ void stage_copy(
    uint32_t sstage,
    const __half* __restrict__ A, int lda,
    const __half* __restrict__ B, int ldb, int k0, int tid)
{
    #pragma unroll
    for (int i = 0; i < 2; i++) {
        int c = tid + i * 256;
        int row = c >> 2;
        int seg = c & 3;
        uint32_t so = row * 80 + seg * 16;
        CPA16(sstage +              so, A + (size_t)row * lda + k0 + seg * 8);
        CPA16(sstage + TILE_BYTES + so, B + (size_t)row * ldb + k0 + seg * 8);
    }
}

__device__ __forceinline__ void compute_stage(
    uint32_t sstage, uint32_t a_off, uint32_t b_off, float acc[4][4][4])
{
    #pragma unroll
    for (int ks = 0; ks < 2; ks++) {
        uint32_t ah[4][4], bh[2][4];
        #pragma unroll
        for (int mf = 0; mf < 4; mf++)
            LDSM4(ah[mf], sstage + a_off + mf * 1280 + ks * 32);
        #pragma unroll
        for (int np = 0; np < 2; np++)
            LDSM4(bh[np], sstage + TILE_BYTES + b_off + np * 1280 + ks * 32);
        #pragma unroll
        for (int mf = 0; mf < 4; mf++) {
            #pragma unroll
            for (int nf = 0; nf < 4; nf++) {
                MMA16816(acc[mf][nf], ah[mf],
                         bh[nf >> 1][(nf & 1) * 2], bh[nf >> 1][(nf & 1) * 2 + 1]);
            }
        }
    }
}

// ---------------------------------------------------------------------------
// proj_gemm: grid (64, 6). slabs: 0=Q(fp16) 1=K(fp16) 2..5 = V/G (fp32)
// ---------------------------------------------------------------------------
__global__ __launch_bounds__(256) void proj_gemm(
    const float* __restrict__ bq, const float* __restrict__ bk,
    const float* __restrict__ bv, const float* __restrict__ bg)
{
    extern __shared__ char smraw[];
    uint32_t sbase = smem_u32(smraw);
    const int tid = threadIdx.x;
    const int m0 = blockIdx.x * 128;
    const int slab = blockIdx.y;
    const int nbase = slab * 128;

    const __half* A = g_Xh + (size_t)m0 * DD;
    const __half* B = g_Wt + (size_t)nbase * DD;

    const int warp = tid >> 5, lane = tid & 31;
    const int lr = lane & 7, gq = lane >> 3;
    const int wm = (warp & 1) * 64, wn = (warp >> 1) * 32;
    const uint32_t a_off = (wm + lr + (gq & 1) * 8) * 80 + (gq >> 1) * 16;
    const uint32_t b_off = (wn + lr + (gq >> 1) * 8) * 80 + (gq & 1) * 16;

    float acc[4][4][4] = {};

    stage_copy(sbase, A, DD, B, DD, 0, tid);
    CP_COMMIT();
    for (int kb = 0; kb < 32; kb++) {
        if (kb + 1 < 32) {
            stage_copy(sbase + ((kb + 1) & 1) * STAGE_BYTES,
                       A, DD, B, DD, (kb + 1) * 32, tid);
            CP_COMMIT();
            CP_WAIT1();
        } else {
            CP_WAIT0();
        }
        __syncthreads();
        compute_stage(sbase + (kb & 1) * STAGE_BYTES, a_off, b_off, acc);
        __syncthreads();
    }

    const int mrow = lane >> 2, ncol = (lane & 3) * 2;
    const float* bias;
    switch (slab) {
        case 0:  bias = bq; break;
        case 1:  bias = bk; break;
        case 2: case 3: bias = bv; break;
        default: bias = bg; break;
    }
    const int nb_off = (slab == 3 || slab == 5) ? 128 : 0;

    #pragma unroll
    for (int mf = 0; mf < 4; mf++) {
        #pragma unroll
        for (int nf = 0; nf < 4; nf++) {
            int m = m0 + wm + mf * 16 + mrow;
            int n = nb_off + wn + nf * 8 + ncol;
            float b0 = bias[n], b1 = bias[n + 1];
            float v00 = acc[mf][nf][0] + b0, v01 = acc[mf][nf][1] + b1;
            float v10 = acc[mf][nf][2] + b0, v11 = acc[mf][nf][3] + b1;
            if (slab == 0) {
                *(uint32_t*)&g_Qh[(size_t)m * DQKC + n] = pack2h(v00, v01);
                *(uint32_t*)&g_Qh[(size_t)(m + 8) * DQKC + n] = pack2h(v10, v11);
            } else if (slab == 1) {
                *(uint32_t*)&g_Kh[(size_t)m * DQKC + n] = pack2h(v00, v01);
                *(uint32_t*)&g_Kh[(size_t)(m + 8) * DQKC + n] = pack2h(v10, v11);
            } else {
                float* outp = (slab < 4) ? g_V : g_G;
                *(float2*)&outp[(size_t)m * DVC + n] = make_float2(v00, v01);
                *(float2*)&outp[(size_t)(m + 8) * DVC + n] = make_float2(v10, v11);
            }
        }
    }
}

// ---------------------------------------------------------------------------
// sumsq: q2/k2 from the ROUNDED fp16 Q/K (consistency with the MMA inputs)
// ---------------------------------------------------------------------------
__global__ __launch_bounds__(256) void sumsq_kernel()
{
    int r = blockIdx.x * 256 + threadIdx.x;
    const __half2* hs = (r < MM) ? (const __half2*)&g_Qh[(size_t)r * DQKC]
                                 : (const __half2*)&g_Kh[(size_t)(r - MM) * DQKC];
    float s = 0.0f;
    #pragma unroll
    for (int k = 0; k < 64; k++) {
        float2 h = __half22float2(hs[k]);
        s = fmaf(h.x, h.x, s); s = fmaf(h.y, h.y, s);
    }
    if (r < MM) g_Q2[r] = s; else g_K2[r - MM] = s;
}

// ---------------------------------------------------------------------------
// vtrans: V fp32 -> Vt[b][n][s] fp16
// ---------------------------------------------------------------------------
__global__ __launch_bounds__(256) void vtrans_kernel()
{
    __shared__ float ts[32][33];
    const int bx = blockIdx.x;
    const int by = blockIdx.y;
    const int tx = threadIdx.x & 31, ty = threadIdx.x >> 5;
    #pragma unroll
    for (int r = 0; r < 4; r++) {
        int m = by * 32 + ty + r * 8;
        ts[ty + r * 8][tx] = g_V[(size_t)m * DVC + bx * 32 + tx];
    }
    __syncthreads();
    const int m = by * 32 + tx;
    const int batch = m >> 11, srow = m & 2047;
    #pragma unroll
    for (int r = 0; r < 4; r++) {
        int n = bx * 32 + ty + r * 8;
        g_Vt[((size_t)batch * DVC + n) * (size_t)SS + srow] =
            __float2half_rn(ts[tx][ty + r * 8]);
    }
}

// ---------------------------------------------------------------------------
// attn: single-fp16 1-MMA Shepard attention, double-buffered K/V.
// ---------------------------------------------------------------------------
#define QPITCH 272
#define KPITCH 272
#define VPITCH 144
#define WPITCH 144

#define OFF_QH  0
#define OFF_KH0 17408
#define OFF_KH1 34816
#define OFF_VH0 52224
#define OFF_VH1 89088
#define OFF_WH  125952
#define OFF_Q2  135168
#define OFF_K20 135424
#define OFF_K21 135680
#define OFF_WS  135936
#define ATT_SMEM_BYTES 136192

#define WSCALE 1024.0f

__device__ __forceinline__ void attn_load_k(uint32_t sKh, int krow0c, int tid)
{
    #pragma unroll
    for (int i = 0; i < 4; i++) {
        int idx = tid + i * 256;
        int row = idx >> 4, seg = idx & 15;
        CPA16(sKh + row * KPITCH + seg * 16,
              g_Kh + (size_t)(krow0c + row) * DQKC + seg * 8);
    }
}

__device__ __forceinline__ void attn_load_v(uint32_t sVh, int b, int kb, int tid)
{
    #pragma unroll
    for (int i = 0; i < 8; i++) {
        int idx = tid + i * 256;
        int n = idx >> 3, seg = idx & 7;
        CPA16(sVh + n * VPITCH + seg * 16,
              g_Vt + ((size_t)b * DVC + n) * (size_t)SS + kb * 64 + seg * 8);
    }
}

__global__ __launch_bounds__(256) void attn_kernel()
{
    extern __shared__ char smc[];
    const uint32_t sb = smem_u32(smc);
    float* q2s  = (float*)(smc + OFF_Q2);
    float* wsum = (float*)(smc + OFF_WS);

    const int tid  = threadIdx.x;
    const int warp = tid >> 5, lane = tid & 31;
    const int lr = lane & 7, gq = lane >> 3;
    const int mrow = lane >> 2, ncol = (lane & 3) * 2;

    const int b  = blockIdx.x >> 5;
    const int qt = blockIdx.x & 31;
    const int qrow0 = b * SS + qt * 64;
    const int krow0 = b * SS;

    // Q + chunk 0 (group 0), chunk 1 (group 1)
    #pragma unroll
    for (int i = 0; i < 4; i++) {
        int idx = tid + i * 256;
        int row = idx >> 4, seg = idx & 15;
        CPA16(sb + OFF_QH + row * QPITCH + seg * 16,
              g_Qh + (size_t)(qrow0 + row) * DQKC + seg * 8);
    }
    attn_load_k(sb + OFF_KH0, krow0, tid);
    attn_load_v(sb + OFF_VH0, b, 0, tid);
    if (tid < 16) CPA16(sb + OFF_K20 + tid * 16, g_K2 + krow0 + tid * 4);
    CP_COMMIT();
    attn_load_k(sb + OFF_KH1, krow0 + 64, tid);
    attn_load_v(sb + OFF_VH1, b, 1, tid);
    if (tid < 16) CPA16(sb + OFF_K21 + tid * 16, g_K2 + krow0 + 64 + tid * 4);
    CP_COMMIT();
    if (tid < 64) { wsum[tid] = 0.0f; q2s[tid] = g_Q2[qrow0 + tid]; }

    float acc[4][4][4] = {};

    const int wmA = (warp & 1) * 32;
    const int wnA = (warp >> 1) * 16;
    const int wnB = warp * 32;
    const uint32_t aQ = (lr + (gq & 1) * 8) * QPITCH + (gq >> 1) * 16;
    const uint32_t bK = (wnA + lr + (gq >> 1) * 8) * KPITCH + (gq & 1) * 16;
    const uint32_t aW = (lr + (gq & 1) * 8) * WPITCH + (gq >> 1) * 16;
    const uint32_t bV = (wnB + lr + (gq >> 1) * 8) * VPITCH + (gq & 1) * 16;

    for (int kc = 0; kc < 32; kc++) {
        if (kc < 31) CP_WAIT1(); else CP_WAIT0();
        __syncthreads();

        const uint32_t sKH = sb + ((kc & 1) ? OFF_KH1 : OFF_KH0);
        const uint32_t sVH = sb + ((kc & 1) ? OFF_VH1 : OFF_VH0);
        const float* k2s = (const float*)(smc + ((kc & 1) ? OFF_K21 : OFF_K20));

        // ---- Phase A: S = Q @ K^T (64x64, K=128) ----
        float s[2][2][4] = {};
        #pragma unroll
        for (int ks = 0; ks < 8; ks++) {
            uint32_t ah[2][4], bh[4];
            LDSM4(ah[0], sb + OFF_QH + aQ + (wmA +  0) * QPITCH + ks * 32);
            LDSM4(ah[1], sb + OFF_QH + aQ + (wmA + 16) * QPITCH + ks * 32);
            LDSM4(bh, sKH + bK + ks * 32);
            #pragma unroll
            for (int mf = 0; mf < 2; mf++) {
                #pragma unroll
                for (int nf = 0; nf < 2; nf++)
                    MMA16816(s[mf][nf], ah[mf], bh[nf * 2], bh[nf * 2 + 1]);
            }
        }

        // ---- w = WSCALE/max(d2,1e-16); fp16-round; sum ROUNDED w ----
        #pragma unroll
        for (int mf = 0; mf < 2; mf++) {
            int r0 = wmA + mf * 16 + mrow;
            int r1 = r0 + 8;
            float q20 = q2s[r0], q21 = q2s[r1];
            float rs0 = 0.0f, rs1 = 0.0f;
            #pragma unroll
            for (int nf = 0; nf < 2; nf++) {
                int n0 = wnA + nf * 8 + ncol;
                float k20 = k2s[n0], k21 = k2s[n0 + 1];
                float d00 = fmaxf(q20 + k20 - 2.0f * s[mf][nf][0], 0.0f);
                float d01 = fmaxf(q20 + k21 - 2.0f * s[mf][nf][1], 0.0f);
                float d10 = fmaxf(q21 + k20 - 2.0f * s[mf][nf][2], 0.0f);
                float d11 = fmaxf(q21 + k21 - 2.0f * s[mf][nf][3], 0.0f);
                __half h00 = __float2half_rn(WSCALE / fmaxf(d00, 1e-16f));
                __half h01 = __float2half_rn(WSCALE / fmaxf(d01, 1e-16f));
                __half h10 = __float2half_rn(WSCALE / fmaxf(d10, 1e-16f));
                __half h11 = __float2half_rn(WSCALE / fmaxf(d11, 1e-16f));
                __half2 p0(h00, h01), p1(h10, h11);
                *(uint32_t*)(smc + OFF_WH + r0 * WPITCH + n0 * 2) =
                    *reinterpret_cast<uint32_t*>(&p0);
                *(uint32_t*)(smc + OFF_WH + r1 * WPITCH + n0 * 2) =
                    *reinterpret_cast<uint32_t*>(&p1);
                rs0 += __half2float(h00) + __half2float(h01);
                rs1 += __half2float(h10) + __half2float(h11);
            }
            atomicAdd(&wsum[r0], rs0);
            atomicAdd(&wsum[r1], rs1);
        }
        __syncthreads();

        // ---- Phase B: acc += w @ V (64x256, K=64 keys) ----
        #pragma unroll
        for (int ks = 0; ks < 4; ks++) {
            uint32_t awh[4][4], bvh[2][4];
            #pragma unroll
            for (int mf = 0; mf < 4; mf++)
                LDSM4(awh[mf], sb + OFF_WH + aW + mf * 16 * WPITCH + ks * 32);
            #pragma unroll
            for (int np = 0; np < 2; np++)
                LDSM4(bvh[np], sVH + bV + np * 16 * VPITCH + ks * 32);
            #pragma unroll
            for (int mf = 0; mf < 4; mf++) {
                #pragma unroll
                for (int nf = 0; nf < 4; nf++) {
                    MMA16816(acc[mf][nf], awh[mf],
                             bvh[nf >> 1][(nf & 1) * 2], bvh[nf >> 1][(nf & 1) * 2 + 1]);
                }
            }
        }
        __syncthreads();

        // prefetch chunk kc+2 into freed buffers
        if (kc + 2 < 32) {
            uint32_t dKH = sb + ((kc & 1) ? OFF_KH1 : OFF_KH0);
            uint32_t dVH = sb + ((kc & 1) ? OFF_VH1 : OFF_VH0);
            uint32_t dK2 = sb + ((kc & 1) ? OFF_K21 : OFF_K20);
            attn_load_k(dKH, krow0 + (kc + 2) * 64, tid);
            attn_load_v(dVH, b, kc + 2, tid);
            if (tid < 16) CPA16(dK2 + tid * 16, g_K2 + krow0 + (kc + 2) * 64 + tid * 4);
            CP_COMMIT();
        }
    }

    // ---- Epilogue: normalize (WSCALE cancels), gate with G, pack fp16 ----
    #pragma unroll
    for (int mf = 0; mf < 4; mf++) {
        int lm0 = mf * 16 + mrow;
        float inv0 = 1.0f / wsum[lm0];
        float inv1 = 1.0f / wsum[lm0 + 8];
        size_t gm0 = (size_t)(qrow0 + lm0) * DVC;
        size_t gm1 = gm0 + 8 * DVC;
        #pragma unroll
        for (int nf = 0; nf < 4; nf++) {
            int n = wnB + nf * 8 + ncol;
            float2 gA = *(const float2*)&g_G[gm0 + n];
            float2 gB = *(const float2*)&g_G[gm1 + n];
            *(uint32_t*)&g_Ph[gm0 + n] =
                pack2h(acc[mf][nf][0] * inv0 * gA.x, acc[mf][nf][1] * inv0 * gA.y);
            *(uint32_t*)&g_Ph[gm1 + n] =
                pack2h(acc[mf][nf][2] * inv1 * gB.x, acc[mf][nf][3] * inv1 * gB.y);
        }
    }
}

// ---------------------------------------------------------------------------
// out_gemm: out = X + P @ Wp + bp
// ---------------------------------------------------------------------------
__global__ __launch_bounds__(256) void out_gemm(
    const float* __restrict__ X, const float* __restrict__ bp,
    float* __restrict__ outp)
{
    extern __shared__ char smraw[];
    uint32_t sbase = smem_u32(smraw);
    const int tid = threadIdx.x;
    const int m0 = blockIdx.x * 128;
    const int n0 = blockIdx.y * 128;

    const __half* A = g_Ph + (size_t)m0 * DVC;
    const __half* B = g_Wpt + (size_t)n0 * DVC;

    const int warp = tid >> 5, lane = tid & 31;
    const int lr = lane & 7, gq = lane >> 3;
    const int wm = (warp & 1) * 64, wn = (warp >> 1) * 32;
    const uint32_t a_off = (wm + lr + (gq & 1) * 8) * 80 + (gq >> 1) * 16;
    const uint32_t b_off = (wn + lr + (gq >> 1) * 8) * 80 + (gq & 1) * 16;

    float acc[4][4][4] = {};

    stage_copy(sbase, A, DVC, B, DVC, 0, tid);
    CP_COMMIT();
    for (int kb = 0; kb < 8; kb++) {
        if (kb + 1 < 8) {
            stage_copy(sbase + ((kb + 1) & 1) * STAGE_BYTES,
                       A, DVC, B, DVC, (kb + 1) * 32, tid);
            CP_COMMIT();
            CP_WAIT1();
        } else {
            CP_WAIT0();
        }
        __syncthreads();
        compute_stage(sbase + (kb & 1) * STAGE_BYTES, a_off, b_off, acc);
        __syncthreads();
    }

    const int mrow = lane >> 2, ncol = (lane & 3) * 2;
    #pragma unroll
    for (int mf = 0; mf < 4; mf++) {
        #pragma unroll
        for (int nf = 0; nf < 4; nf++) {
            int m = m0 + wm + mf * 16 + mrow;
            int n = n0 + wn + nf * 8 + ncol;
            float b0 = bp[n], b1 = bp[n + 1];
            float2 x0 = *(const float2*)&X[(size_t)m * DD + n];
            float2 x1 = *(const float2*)&X[(size_t)(m + 8) * DD + n];
            *(float2*)&outp[(size_t)m * DD + n] =
                make_float2(acc[mf][nf][0] + b0 + x0.x, acc[mf][nf][1] + b1 + x0.y);
            *(float2*)&outp[(size_t)(m + 8) * DD + n] =
                make_float2(acc[mf][nf][2] + b0 + x1.x, acc[mf][nf][3] + b1 + x1.y);
        }
    }
}

// ---------------------------------------------------------------------------
extern "C" void kernel_launch(void* const* d_in, const int* in_sizes, int n_in,
                              void* d_out, int out_size)
{
    const float* X  = (const float*)d_in[0];
    const float* Wq = (const float*)d_in[1];
    const float* bq = (const float*)d_in[2];
    const float* Wk = (const float*)d_in[3];
    const float* bk = (const float*)d_in[4];
    const float* Wv = (const float*)d_in[5];
    const float* bv = (const float*)d_in[6];
    const float* Wg = (const float*)d_in[7];
    const float* bg = (const float*)d_in[8];
    const float* Wp = (const float*)d_in[9];
    const float* bp = (const float*)d_in[10];
    float* out = (float*)d_out;

    cudaFuncSetAttribute(proj_gemm, cudaFuncAttributeMaxDynamicSharedMemorySize, GEMM_SMEM_BYTES);
    cudaFuncSetAttribute(out_gemm,  cudaFuncAttributeMaxDynamicSharedMemorySize, GEMM_SMEM_BYTES);
    cudaFuncSetAttribute(attn_kernel, cudaFuncAttributeMaxDynamicSharedMemorySize, ATT_SMEM_BYTES);

    split_x_kernel<<<MM * DD / 1024, 256>>>(X);
    split_w_kernel<<<(NPROJ * DD + DD * DVC) / 256, 256>>>(Wq, Wk, Wv, Wg, Wp);
    proj_gemm<<<dim3(64, 6), 256, GEMM_SMEM_BYTES>>>(bq, bk, bv, bg);
    sumsq_kernel<<<64, 256>>>();
    vtrans_kernel<<<dim3(8, 256), 256>>>();
    attn_kernel<<<128, 256, ATT_SMEM_BYTES>>>();
    out_gemm<<<dim3(64, 8), 256, GEMM_SMEM_BYTES>>>(X, bp, out);
}

// round 8
// speedup vs baseline: 5.9060x; 1.3724x over previous
#include <cuda_runtime.h>
#include <cuda_fp16.h>
#include <cstdint>

#define BB   4
#define SS   2048
#define DD   1024
#define DQKC 128
#define DVC  256
#define MM   (BB * SS)   // 8192
#define NPROJ 768

// ---------------------------------------------------------------------------
// Device scratch (all fp16 operands)
// ---------------------------------------------------------------------------
__device__ __align__(256) __half g_Xh[MM * DD];
__device__ __align__(256) __half g_Wt[NPROJ * DD];      // [n][k]
__device__ __align__(256) __half g_Wpt[DD * DVC];       // [n][k]
__device__ __align__(256) __half g_Qh[MM * DQKC];
__device__ __align__(256) __half g_Kh[MM * DQKC];
__device__ __align__(256) __half g_Vt[BB * DVC * SS];   // [b][n][s]
__device__ __align__(256) __half g_Gh[MM * DVC];
__device__ __align__(256) __half g_Ph[MM * DVC];        // (AV*G)
__device__ __align__(256) float g_Q2[MM];
__device__ __align__(256) float g_K2[MM];

// ---------------------------------------------------------------------------
// PTX helpers
// ---------------------------------------------------------------------------
__device__ __forceinline__ uint32_t smem_u32(const void* p) {
    uint32_t a;
    asm("{ .reg .u64 t; cvta.to.shared.u64 t, %1; cvt.u32.u64 %0, t; }"
        : "=r"(a) : "l"(p));
    return a;
}

#define LDSM4(r, addr) \
    asm volatile("ldmatrix.sync.aligned.m8n8.x4.shared.b16 {%0,%1,%2,%3}, [%4];" \
        : "=r"((r)[0]), "=r"((r)[1]), "=r"((r)[2]), "=r"((r)[3]) : "r"(addr))

#define MMA16816(c, a, b0, b1) \
    asm volatile("mma.sync.aligned.m16n8k16.row.col.f32.f16.f16.f32 " \
        "{%0,%1,%2,%3}, {%4,%5,%6,%7}, {%8,%9}, {%0,%1,%2,%3};" \
        : "+f"((c)[0]), "+f"((c)[1]), "+f"((c)[2]), "+f"((c)[3]) \
        : "r"((a)[0]), "r"((a)[1]), "r"((a)[2]), "r"((a)[3]), "r"(b0), "r"(b1))

#define CPA16(s, g) \
    asm volatile("cp.async.ca.shared.global [%0], [%1], 16;" :: "r"(s), "l"(g) : "memory")
#define CP_COMMIT() asm volatile("cp.async.commit_group;" ::: "memory")
#define CP_WAIT1()  asm volatile("cp.async.wait_group 1;" ::: "memory")
#define CP_WAIT0()  asm volatile("cp.async.wait_group 0;" ::: "memory")

__device__ __forceinline__ uint32_t pack2h(float a, float b) {
    __half2 hp(__float2half_rn(a), __float2half_rn(b));
    return *reinterpret_cast<uint32_t*>(&hp);
}

// ---------------------------------------------------------------------------
// Prep
// ---------------------------------------------------------------------------
__global__ __launch_bounds__(256) void split_x_kernel(const float* __restrict__ X)
{
    int i = (blockIdx.x * 256 + threadIdx.x) * 4;
    float4 v = *(const float4*)&X[i];
    *(uint2*)&g_Xh[i] = make_uint2(pack2h(v.x, v.y), pack2h(v.z, v.w));
}

__global__ __launch_bounds__(256) void split_w_kernel(
    const float* __restrict__ Wq, const float* __restrict__ Wk,
    const float* __restrict__ Wv, const float* __restrict__ Wg,
    const float* __restrict__ Wp)
{
    int idx = blockIdx.x * 256 + threadIdx.x;
    if (idx < NPROJ * DD) {
        int n = idx >> 10, k = idx & 1023;
        const float* W; int col; int ncols;
        if (n < 128)      { W = Wq; col = n;       ncols = 128; }
        else if (n < 256) { W = Wk; col = n - 128; ncols = 128; }
        else if (n < 512) { W = Wv; col = n - 256; ncols = 256; }
        else              { W = Wg; col = n - 512; ncols = 256; }
        g_Wt[idx] = __float2half_rn(W[k * ncols + col]);
    } else {
        int j = idx - NPROJ * DD;
        int n = j >> 8, k = j & 255;
        g_Wpt[j] = __float2half_rn(Wp[k * DD + n]);
    }
}

// ---------------------------------------------------------------------------
// GEMM machinery: single fp16, BK=64, pitch-144 tiles, 2 stages.
// ---------------------------------------------------------------------------
#define TILE_BYTES   18432            // 128 rows * 144B (64 fp16 + 16 pad)
#define STAGE_BYTES  (2 * TILE_BYTES) // 36864
#define GEMM_SMEM_BYTES (2 * STAGE_BYTES)   // 73728

__device__ __forceinline__ void stage_copy(
    uint32_t sstage,
    const __half* __restrict__ A, int lda,
    const __half* __restrict__ B, int ldb, int k0, int tid)
{
    #pragma unroll
    for (int i = 0; i < 4; i++) {
        int idx = tid + i * 256;       // 0..1023
        int row = idx >> 3;
        int seg = idx & 7;
        uint32_t so = row * 144 + seg * 16;
        CPA16(sstage +              so, A + (size_t)row * lda + k0 + seg * 8);
        CPA16(sstage + TILE_BYTES + so, B + (size_t)row * ldb + k0 + seg * 8);
    }
}

__device__ __forceinline__ void compute_stage(
    uint32_t sstage, uint32_t a_off, uint32_t b_off, float acc[4][4][4])
{
    #pragma unroll
    for (int ks = 0; ks < 4; ks++) {
        uint32_t ah[4][4], bh[2][4];
        #pragma unroll
        for (int mf = 0; mf < 4; mf++)
            LDSM4(ah[mf], sstage + a_off + mf * 2304 + ks * 32);
        #pragma unroll
        for (int np = 0; np < 2; np++)
            LDSM4(bh[np], sstage + TILE_BYTES + b_off + np * 2304 + ks * 32);
        #pragma unroll
        for (int mf = 0; mf < 4; mf++) {
            #pragma unroll
            for (int nf = 0; nf < 4; nf++) {
                MMA16816(acc[mf][nf], ah[mf],
                         bh[nf >> 1][(nf & 1) * 2], bh[nf >> 1][(nf & 1) * 2 + 1]);
            }
        }
    }
}

// ---------------------------------------------------------------------------
// proj_gemm: grid (64, 6), 256 threads. Fused epilogues:
//   slab 0/1: Q/K fp16 + q2/k2 row sums (from ROUNDED values)
//   slab 2/3: V fp16, transposed in SMEM -> g_Vt[b][n][s]
//   slab 4/5: G fp16
// ---------------------------------------------------------------------------
__global__ __launch_bounds__(256) void proj_gemm(
    const float* __restrict__ bq, const float* __restrict__ bk,
    const float* __restrict__ bv, const float* __restrict__ bg)
{
    extern __shared__ char smraw[];
    __shared__ float sq2[128];
    uint32_t sbase = smem_u32(smraw);
    const int tid = threadIdx.x;
    const int m0 = blockIdx.x * 128;
    const int slab = blockIdx.y;
    const int nbase = slab * 128;

    if (tid < 128) sq2[tid] = 0.0f;

    const __half* A = g_Xh + (size_t)m0 * DD;
    const __half* B = g_Wt + (size_t)nbase * DD;

    const int warp = tid >> 5, lane = tid & 31;
    const int lr = lane & 7, gq = lane >> 3;
    const int wm = (warp & 1) * 64, wn = (warp >> 1) * 32;
    const uint32_t a_off = (wm + lr + (gq & 1) * 8) * 144 + (gq >> 1) * 16;
    const uint32_t b_off = (wn + lr + (gq >> 1) * 8) * 144 + (gq & 1) * 16;

    float acc[4][4][4] = {};

    stage_copy(sbase, A, DD, B, DD, 0, tid);
    CP_COMMIT();
    for (int kb = 0; kb < 16; kb++) {
        if (kb + 1 < 16) {
            stage_copy(sbase + ((kb + 1) & 1) * STAGE_BYTES,
                       A, DD, B, DD, (kb + 1) * 64, tid);
            CP_COMMIT();
            CP_WAIT1();
        } else {
            CP_WAIT0();
        }
        __syncthreads();
        compute_stage(sbase + (kb & 1) * STAGE_BYTES, a_off, b_off, acc);
        __syncthreads();
    }

    const int mrow = lane >> 2, ncol = (lane & 3) * 2;

    if (slab < 2) {
        // ---- Q / K: fp16 store + rounded row sum-of-squares ----
        const float* bias = (slab == 0) ? bq : bk;
        __half* dst = (slab == 0) ? g_Qh : g_Kh;
        float part[4][2] = {};
        #pragma unroll
        for (int mf = 0; mf < 4; mf++) {
            int lm = wm + mf * 16 + mrow;
            #pragma unroll
            for (int nf = 0; nf < 4; nf++) {
                int n = wn + nf * 8 + ncol;
                float b0 = bias[n], b1 = bias[n + 1];
                __half h00 = __float2half_rn(acc[mf][nf][0] + b0);
                __half h01 = __float2half_rn(acc[mf][nf][1] + b1);
                __half h10 = __float2half_rn(acc[mf][nf][2] + b0);
                __half h11 = __float2half_rn(acc[mf][nf][3] + b1);
                __half2 p0(h00, h01), p1(h10, h11);
                *(uint32_t*)&dst[(size_t)(m0 + lm) * DQKC + n] =
                    *reinterpret_cast<uint32_t*>(&p0);
                *(uint32_t*)&dst[(size_t)(m0 + lm + 8) * DQKC + n] =
                    *reinterpret_cast<uint32_t*>(&p1);
                float f00 = __half2float(h00), f01 = __half2float(h01);
                float f10 = __half2float(h10), f11 = __half2float(h11);
                part[mf][0] += f00 * f00 + f01 * f01;
                part[mf][1] += f10 * f10 + f11 * f11;
            }
        }
        #pragma unroll
        for (int mf = 0; mf < 4; mf++) {
            float s0 = part[mf][0], s1 = part[mf][1];
            s0 += __shfl_xor_sync(0xffffffffu, s0, 1);
            s0 += __shfl_xor_sync(0xffffffffu, s0, 2);
            s1 += __shfl_xor_sync(0xffffffffu, s1, 1);
            s1 += __shfl_xor_sync(0xffffffffu, s1, 2);
            if ((lane & 3) == 0) {
                int lm = wm + mf * 16 + mrow;
                atomicAdd(&sq2[lm], s0);
                atomicAdd(&sq2[lm + 8], s1);
            }
        }
        __syncthreads();
        if (tid < 128) {
            if (slab == 0) g_Q2[m0 + tid] = sq2[tid];
            else           g_K2[m0 + tid] = sq2[tid];
        }
    } else if (slab < 4) {
        // ---- V: fp16 into SMEM, then transposed write to g_Vt ----
        __half* Vs = (__half*)smraw;     // pitch 130 halfs
        const int VSP = 130;
        #pragma unroll
        for (int mf = 0; mf < 4; mf++) {
            int lm = wm + mf * 16 + mrow;
            #pragma unroll
            for (int nf = 0; nf < 4; nf++) {
                int n = wn + nf * 8 + ncol;
                float b0 = bv[((slab == 3) ? 128 : 0) + n];
                float b1 = bv[((slab == 3) ? 128 : 0) + n + 1];
                *(uint32_t*)&Vs[lm * VSP + n] =
                    pack2h(acc[mf][nf][0] + b0, acc[mf][nf][1] + b1);
                *(uint32_t*)&Vs[(lm + 8) * VSP + n] =
                    pack2h(acc[mf][nf][2] + b0, acc[mf][nf][3] + b1);
            }
        }
        __syncthreads();
        const int batch = m0 >> 11;
        const int mloc  = m0 & 2047;
        const int nbo   = (slab == 3) ? 128 : 0;
        #pragma unroll
        for (int i = 0; i < 8; i++) {
            int idx = tid + i * 256;       // 0..2047
            int n = idx >> 4;              // 0..127
            int mseg = idx & 15;           // 0..15 (8 m each)
            __half tmp[8];
            #pragma unroll
            for (int j = 0; j < 8; j++)
                tmp[j] = Vs[(mseg * 8 + j) * VSP + n];
            *(uint4*)&g_Vt[((size_t)batch * DVC + nbo + n) * SS + mloc + mseg * 8] =
                *(uint4*)tmp;
        }
    } else {
        // ---- G: fp16 store ----
        const int nbo = (slab == 5) ? 128 : 0;
        #pragma unroll
        for (int mf = 0; mf < 4; mf++) {
            int m = m0 + wm + mf * 16 + mrow;
            #pragma unroll
            for (int nf = 0; nf < 4; nf++) {
                int n = wn + nf * 8 + ncol;
                float b0 = bg[nbo + n], b1 = bg[nbo + n + 1];
                *(uint32_t*)&g_Gh[(size_t)m * DVC + nbo + n] =
                    pack2h(acc[mf][nf][0] + b0, acc[mf][nf][1] + b1);
                *(uint32_t*)&g_Gh[(size_t)(m + 8) * DVC + nbo + n] =
                    pack2h(acc[mf][nf][2] + b0, acc[mf][nf][3] + b1);
            }
        }
    }
}

// ---------------------------------------------------------------------------
// attn: single-fp16 1-MMA Shepard attention, double-buffered K/V.
// ---------------------------------------------------------------------------
#define QPITCH 272
#define KPITCH 272
#define VPITCH 144
#define WPITCH 144

#define OFF_QH  0
#define OFF_KH0 17408
#define OFF_KH1 34816
#define OFF_VH0 52224
#define OFF_VH1 89088
#define OFF_WH  125952
#define OFF_Q2  135168
#define OFF_K20 135424
#define OFF_K21 135680
#define OFF_WS  135936
#define ATT_SMEM_BYTES 136192

#define WSCALE 1024.0f

__device__ __forceinline__ void attn_load_k(uint32_t sKh, int krow0c, int tid)
{
    #pragma unroll
    for (int i = 0; i < 4; i++) {
        int idx = tid + i * 256;
        int row = idx >> 4, seg = idx & 15;
        CPA16(sKh + row * KPITCH + seg * 16,
              g_Kh + (size_t)(krow0c + row) * DQKC + seg * 8);
    }
}

__device__ __forceinline__ void attn_load_v(uint32_t sVh, int b, int kb, int tid)
{
    #pragma unroll
    for (int i = 0; i < 8; i++) {
        int idx = tid + i * 256;
        int n = idx >> 3, seg = idx & 7;
        CPA16(sVh + n * VPITCH + seg * 16,
              g_Vt + ((size_t)b * DVC + n) * (size_t)SS + kb * 64 + seg * 8);
    }
}

__global__ __launch_bounds__(256) void attn_kernel()
{
    extern __shared__ char smc[];
    const uint32_t sb = smem_u32(smc);
    float* q2s  = (float*)(smc + OFF_Q2);
    float* wsum = (float*)(smc + OFF_WS);

    const int tid  = threadIdx.x;
    const int warp = tid >> 5, lane = tid & 31;
    const int lr = lane & 7, gq = lane >> 3;
    const int mrow = lane >> 2, ncol = (lane & 3) * 2;

    const int b  = blockIdx.x >> 5;
    const int qt = blockIdx.x & 31;
    const int qrow0 = b * SS + qt * 64;
    const int krow0 = b * SS;

    #pragma unroll
    for (int i = 0; i < 4; i++) {
        int idx = tid + i * 256;
        int row = idx >> 4, seg = idx & 15;
        CPA16(sb + OFF_QH + row * QPITCH + seg * 16,
              g_Qh + (size_t)(qrow0 + row) * DQKC + seg * 8);
    }
    attn_load_k(sb + OFF_KH0, krow0, tid);
    attn_load_v(sb + OFF_VH0, b, 0, tid);
    if (tid < 16) CPA16(sb + OFF_K20 + tid * 16, g_K2 + krow0 + tid * 4);
    CP_COMMIT();
    attn_load_k(sb + OFF_KH1, krow0 + 64, tid);
    attn_load_v(sb + OFF_VH1, b, 1, tid);
    if (tid < 16) CPA16(sb + OFF_K21 + tid * 16, g_K2 + krow0 + 64 + tid * 4);
    CP_COMMIT();
    if (tid < 64) { wsum[tid] = 0.0f; q2s[tid] = g_Q2[qrow0 + tid]; }

    float acc[4][4][4] = {};

    const int wmA = (warp & 1) * 32;
    const int wnA = (warp >> 1) * 16;
    const int wnB = warp * 32;
    const uint32_t aQ = (lr + (gq & 1) * 8) * QPITCH + (gq >> 1) * 16;
    const uint32_t bK = (wnA + lr + (gq >> 1) * 8) * KPITCH + (gq & 1) * 16;
    const uint32_t aW = (lr + (gq & 1) * 8) * WPITCH + (gq >> 1) * 16;
    const uint32_t bV = (wnB + lr + (gq >> 1) * 8) * VPITCH + (gq & 1) * 16;

    for (int kc = 0; kc < 32; kc++) {
        if (kc < 31) CP_WAIT1(); else CP_WAIT0();
        __syncthreads();

        const uint32_t sKH = sb + ((kc & 1) ? OFF_KH1 : OFF_KH0);
        const uint32_t sVH = sb + ((kc & 1) ? OFF_VH1 : OFF_VH0);
        const float* k2s = (const float*)(smc + ((kc & 1) ? OFF_K21 : OFF_K20));

        // ---- Phase A: S = Q @ K^T (64x64, K=128) ----
        float s[2][2][4] = {};
        #pragma unroll
        for (int ks = 0; ks < 8; ks++) {
            uint32_t ah[2][4], bh[4];
            LDSM4(ah[0], sb + OFF_QH + aQ + (wmA +  0) * QPITCH + ks * 32);
            LDSM4(ah[1], sb + OFF_QH + aQ + (wmA + 16) * QPITCH + ks * 32);
            LDSM4(bh, sKH + bK + ks * 32);
            #pragma unroll
            for (int mf = 0; mf < 2; mf++) {
                #pragma unroll
                for (int nf = 0; nf < 2; nf++)
                    MMA16816(s[mf][nf], ah[mf], bh[nf * 2], bh[nf * 2 + 1]);
            }
        }

        // ---- w = WSCALE/max(d2,eps); fp16-round; quad-reduced row sums ----
        #pragma unroll
        for (int mf = 0; mf < 2; mf++) {
            int r0 = wmA + mf * 16 + mrow;
            int r1 = r0 + 8;
            float q20 = q2s[r0], q21 = q2s[r1];
            float rs0 = 0.0f, rs1 = 0.0f;
            #pragma unroll
            for (int nf = 0; nf < 2; nf++) {
                int n0 = wnA + nf * 8 + ncol;
                float k20 = k2s[n0], k21 = k2s[n0 + 1];
                float d00 = fmaxf(q20 + k20 - 2.0f * s[mf][nf][0], 0.0f);
                float d01 = fmaxf(q20 + k21 - 2.0f * s[mf][nf][1], 0.0f);
                float d10 = fmaxf(q21 + k20 - 2.0f * s[mf][nf][2], 0.0f);
                float d11 = fmaxf(q21 + k21 - 2.0f * s[mf][nf][3], 0.0f);
                __half h00 = __float2half_rn(WSCALE / fmaxf(d00, 1e-16f));
                __half h01 = __float2half_rn(WSCALE / fmaxf(d01, 1e-16f));
                __half h10 = __float2half_rn(WSCALE / fmaxf(d10, 1e-16f));
                __half h11 = __float2half_rn(WSCALE / fmaxf(d11, 1e-16f));
                __half2 p0(h00, h01), p1(h10, h11);
                *(uint32_t*)(smc + OFF_WH + r0 * WPITCH + n0 * 2) =
                    *reinterpret_cast<uint32_t*>(&p0);
                *(uint32_t*)(smc + OFF_WH + r1 * WPITCH + n0 * 2) =
                    *reinterpret_cast<uint32_t*>(&p1);
                rs0 += __half2float(h00) + __half2float(h01);
                rs1 += __half2float(h10) + __half2float(h11);
            }
            rs0 += __shfl_xor_sync(0xffffffffu, rs0, 1);
            rs0 += __shfl_xor_sync(0xffffffffu, rs0, 2);
            rs1 += __shfl_xor_sync(0xffffffffu, rs1, 1);
            rs1 += __shfl_xor_sync(0xffffffffu, rs1, 2);
            if ((lane & 3) == 0) {
                atomicAdd(&wsum[r0], rs0);
                atomicAdd(&wsum[r1], rs1);
            }
        }
        __syncthreads();

        // ---- Phase B: acc += w @ V (64x256, K=64 keys) ----
        #pragma unroll
        for (int ks = 0; ks < 4; ks++) {
            uint32_t awh[4][4], bvh[2][4];
            #pragma unroll
            for (int mf = 0; mf < 4; mf++)
                LDSM4(awh[mf], sb + OFF_WH + aW + mf * 16 * WPITCH + ks * 32);
            #pragma unroll
            for (int np = 0; np < 2; np++)
                LDSM4(bvh[np], sVH + bV + np * 16 * VPITCH + ks * 32);
            #pragma unroll
            for (int mf = 0; mf < 4; mf++) {
                #pragma unroll
                for (int nf = 0; nf < 4; nf++) {
                    MMA16816(acc[mf][nf], awh[mf],
                             bvh[nf >> 1][(nf & 1) * 2], bvh[nf >> 1][(nf & 1) * 2 + 1]);
                }
            }
        }
        __syncthreads();

        if (kc + 2 < 32) {
            uint32_t dKH = sb + ((kc & 1) ? OFF_KH1 : OFF_KH0);
            uint32_t dVH = sb + ((kc & 1) ? OFF_VH1 : OFF_VH0);
            uint32_t dK2 = sb + ((kc & 1) ? OFF_K21 : OFF_K20);
            attn_load_k(dKH, krow0 + (kc + 2) * 64, tid);
            attn_load_v(dVH, b, kc + 2, tid);
            if (tid < 16) CPA16(dK2 + tid * 16, g_K2 + krow0 + (kc + 2) * 64 + tid * 4);
            CP_COMMIT();
        }
    }

    // ---- Epilogue: normalize (WSCALE cancels), gate with fp16 G, pack P ----
    #pragma unroll
    for (int mf = 0; mf < 4; mf++) {
        int lm0 = mf * 16 + mrow;
        float inv0 = 1.0f / wsum[lm0];
        float inv1 = 1.0f / wsum[lm0 + 8];
        size_t gm0 = (size_t)(qrow0 + lm0) * DVC;
        size_t gm1 = gm0 + 8 * DVC;
        #pragma unroll
        for (int nf = 0; nf < 4; nf++) {
            int n = wnB + nf * 8 + ncol;
            float2 gA = __half22float2(*(const __half2*)&g_Gh[gm0 + n]);
            float2 gB = __half22float2(*(const __half2*)&g_Gh[gm1 + n]);
            *(uint32_t*)&g_Ph[gm0 + n] =
                pack2h(acc[mf][nf][0] * inv0 * gA.x, acc[mf][nf][1] * inv0 * gA.y);
            *(uint32_t*)&g_Ph[gm1 + n] =
                pack2h(acc[mf][nf][2] * inv1 * gB.x, acc[mf][nf][3] * inv1 * gB.y);
        }
    }
}

// ---------------------------------------------------------------------------
// out_gemm: out = X + P @ Wp + bp   (BK=64, 4 k-blocks)
// ---------------------------------------------------------------------------
__global__ __launch_bounds__(256) void out_gemm(
    const float* __restrict__ X, const float* __restrict__ bp,
    float* __restrict__ outp)
{
    extern __shared__ char smraw[];
    uint32_t sbase = smem_u32(smraw);
    const int tid = threadIdx.x;
    const int m0 = blockIdx.x * 128;
    const int n0 = blockIdx.y * 128;

    const __half* A = g_Ph + (size_t)m0 * DVC;
    const __half* B = g_Wpt + (size_t)n0 * DVC;

    const int warp = tid >> 5, lane = tid & 31;
    const int lr = lane & 7, gq = lane >> 3;
    const int wm = (warp & 1) * 64, wn = (warp >> 1) * 32;
    const uint32_t a_off = (wm + lr + (gq & 1) * 8) * 144 + (gq >> 1) * 16;
    const uint32_t b_off = (wn + lr + (gq >> 1) * 8) * 144 + (gq & 1) * 16;

    float acc[4][4][4] = {};

    stage_copy(sbase, A, DVC, B, DVC, 0, tid);
    CP_COMMIT();
    for (int kb = 0; kb < 4; kb++) {
        if (kb + 1 < 4) {
            stage_copy(sbase + ((kb + 1) & 1) * STAGE_BYTES,
                       A, DVC, B, DVC, (kb + 1) * 64, tid);
            CP_COMMIT();
            CP_WAIT1();
        } else {
            CP_WAIT0();
        }
        __syncthreads();
        compute_stage(sbase + (kb & 1) * STAGE_BYTES, a_off, b_off, acc);
        __syncthreads();
    }

    const int mrow = lane >> 2, ncol = (lane & 3) * 2;
    #pragma unroll
    for (int mf = 0; mf < 4; mf++) {
        #pragma unroll
        for (int nf = 0; nf < 4; nf++) {
            int m = m0 + wm + mf * 16 + mrow;
            int n = n0 + wn + nf * 8 + ncol;
            float b0 = bp[n], b1 = bp[n + 1];
            float2 x0 = *(const float2*)&X[(size_t)m * DD + n];
            float2 x1 = *(const float2*)&X[(size_t)(m + 8) * DD + n];
            *(float2*)&outp[(size_t)m * DD + n] =
                make_float2(acc[mf][nf][0] + b0 + x0.x, acc[mf][nf][1] + b1 + x0.y);
            *(float2*)&outp[(size_t)(m + 8) * DD + n] =
                make_float2(acc[mf][nf][2] + b0 + x1.x, acc[mf][nf][3] + b1 + x1.y);
        }
    }
}

// ---------------------------------------------------------------------------
extern "C" void kernel_launch(void* const* d_in, const int* in_sizes, int n_in,
                              void* d_out, int out_size)
{
    const float* X  = (const float*)d_in[0];
    const float* Wq = (const float*)d_in[1];
    const float* bq = (const float*)d_in[2];
    const float* Wk = (const float*)d_in[3];
    const float* bk = (const float*)d_in[4];
    const float* Wv = (const float*)d_in[5];
    const float* bv = (const float*)d_in[6];
    const float* Wg = (const float*)d_in[7];
    const float* bg = (const float*)d_in[8];
    const float* Wp = (const float*)d_in[9];
    const float* bp = (const float*)d_in[10];
    float* out = (float*)d_out;

    cudaFuncSetAttribute(proj_gemm, cudaFuncAttributeMaxDynamicSharedMemorySize, GEMM_SMEM_BYTES);
    cudaFuncSetAttribute(out_gemm,  cudaFuncAttributeMaxDynamicSharedMemorySize, GEMM_SMEM_BYTES);
    cudaFuncSetAttribute(attn_kernel, cudaFuncAttributeMaxDynamicSharedMemorySize, ATT_SMEM_BYTES);

    split_x_kernel<<<MM * DD / 1024, 256>>>(X);
    split_w_kernel<<<(NPROJ * DD + DD * DVC) / 256, 256>>>(Wq, Wk, Wv, Wg, Wp);
    proj_gemm<<<dim3(64, 6), 256, GEMM_SMEM_BYTES>>>(bq, bk, bv, bg);
    attn_kernel<<<128, 256, ATT_SMEM_BYTES>>>();
    out_gemm<<<dim3(64, 8), 256, GEMM_SMEM_BYTES>>>(X, bp, out);
}

// round 9
// speedup vs baseline: 6.3736x; 1.0792x over previous
#include <cuda_runtime.h>
#include <cuda_fp16.h>
#include <cstdint>

#define BB   4
#define SS   2048
#define DD   1024
#define DQKC 128
#define DVC  256
#define MM   (BB * SS)   // 8192
#define NPROJ 768

// ---------------------------------------------------------------------------
// Device scratch (all fp16 operands)
// ---------------------------------------------------------------------------
__device__ __align__(256) __half g_Xh[MM * DD];
__device__ __align__(256) __half g_Wt[NPROJ * DD];      // [n][k]
__device__ __align__(256) __half g_Wpt[DD * DVC];       // [n][k]
__device__ __align__(256) __half g_Qh[MM * DQKC];
__device__ __align__(256) __half g_Kh[MM * DQKC];
__device__ __align__(256) __half g_Vt[BB * DVC * SS];   // [b][n][s]
__device__ __align__(256) __half g_Gh[MM * DVC];
__device__ __align__(256) __half g_Ph[MM * DVC];        // (AV*G)
__device__ __align__(256) float g_Q2[MM];
__device__ __align__(256) float g_K2[MM];

// ---------------------------------------------------------------------------
// PTX helpers
// ---------------------------------------------------------------------------
__device__ __forceinline__ uint32_t smem_u32(const void* p) {
    uint32_t a;
    asm("{ .reg .u64 t; cvta.to.shared.u64 t, %1; cvt.u32.u64 %0, t; }"
        : "=r"(a) : "l"(p));
    return a;
}

#define LDSM4(r, addr) \
    asm volatile("ldmatrix.sync.aligned.m8n8.x4.shared.b16 {%0,%1,%2,%3}, [%4];" \
        : "=r"((r)[0]), "=r"((r)[1]), "=r"((r)[2]), "=r"((r)[3]) : "r"(addr))

#define MMA16816(c, a, b0, b1) \
    asm volatile("mma.sync.aligned.m16n8k16.row.col.f32.f16.f16.f32 " \
        "{%0,%1,%2,%3}, {%4,%5,%6,%7}, {%8,%9}, {%0,%1,%2,%3};" \
        : "+f"((c)[0]), "+f"((c)[1]), "+f"((c)[2]), "+f"((c)[3]) \
        : "r"((a)[0]), "r"((a)[1]), "r"((a)[2]), "r"((a)[3]), "r"(b0), "r"(b1))

#define CPA16(s, g) \
    asm volatile("cp.async.ca.shared.global [%0], [%1], 16;" :: "r"(s), "l"(g) : "memory")
#define CP_COMMIT() asm volatile("cp.async.commit_group;" ::: "memory")
#define CP_WAIT1()  asm volatile("cp.async.wait_group 1;" ::: "memory")
#define CP_WAIT0()  asm volatile("cp.async.wait_group 0;" ::: "memory")

__device__ __forceinline__ uint32_t pack2h(float a, float b) {
    __half2 hp(__float2half_rn(a), __float2half_rn(b));
    return *reinterpret_cast<uint32_t*>(&hp);
}

// ---------------------------------------------------------------------------
// Prep
// ---------------------------------------------------------------------------
__global__ __launch_bounds__(256) void split_x_kernel(const float* __restrict__ X)
{
    int i = (blockIdx.x * 256 + threadIdx.x) * 4;
    float4 v = *(const float4*)&X[i];
    *(uint2*)&g_Xh[i] = make_uint2(pack2h(v.x, v.y), pack2h(v.z, v.w));
}

__global__ __launch_bounds__(256) void split_w_kernel(
    const float* __restrict__ Wq, const float* __restrict__ Wk,
    const float* __restrict__ Wv, const float* __restrict__ Wg,
    const float* __restrict__ Wp)
{
    int idx = blockIdx.x * 256 + threadIdx.x;
    if (idx < NPROJ * DD) {
        int n = idx >> 10, k = idx & 1023;
        const float* W; int col; int ncols;
        if (n < 128)      { W = Wq; col = n;       ncols = 128; }
        else if (n < 256) { W = Wk; col = n - 128; ncols = 128; }
        else if (n < 512) { W = Wv; col = n - 256; ncols = 256; }
        else              { W = Wg; col = n - 512; ncols = 256; }
        g_Wt[idx] = __float2half_rn(W[k * ncols + col]);
    } else {
        int j = idx - NPROJ * DD;
        int n = j >> 8, k = j & 255;
        g_Wpt[j] = __float2half_rn(Wp[k * DD + n]);
    }
}

// ---------------------------------------------------------------------------
// GEMM machinery: single fp16, BK=64, pitch-144 tiles, 2 stages.
// ---------------------------------------------------------------------------
#define TILE_BYTES   18432            // 128 rows * 144B
#define STAGE_BYTES  (2 * TILE_BYTES) // 36864
#define GEMM_SMEM_BYTES (2 * STAGE_BYTES)   // 73728

__device__ __forceinline__ void stage_copy(
    uint32_t sstage,
    const __half* __restrict__ A, int lda,
    const __half* __restrict__ B, int ldb, int k0, int tid)
{
    #pragma unroll
    for (int i = 0; i < 4; i++) {
        int idx = tid + i * 256;
        int row = idx >> 3;
        int seg = idx & 7;
        uint32_t so = row * 144 + seg * 16;
        CPA16(sstage +              so, A + (size_t)row * lda + k0 + seg * 8);
        CPA16(sstage + TILE_BYTES + so, B + (size_t)row * ldb + k0 + seg * 8);
    }
}

__device__ __forceinline__ void compute_stage(
    uint32_t sstage, uint32_t a_off, uint32_t b_off, float acc[4][4][4])
{
    #pragma unroll
    for (int ks = 0; ks < 4; ks++) {
        uint32_t ah[4][4], bh[2][4];
        #pragma unroll
        for (int mf = 0; mf < 4; mf++)
            LDSM4(ah[mf], sstage + a_off + mf * 2304 + ks * 32);
        #pragma unroll
        for (int np = 0; np < 2; np++)
            LDSM4(bh[np], sstage + TILE_BYTES + b_off + np * 2304 + ks * 32);
        #pragma unroll
        for (int mf = 0; mf < 4; mf++) {
            #pragma unroll
            for (int nf = 0; nf < 4; nf++) {
                MMA16816(acc[mf][nf], ah[mf],
                         bh[nf >> 1][(nf & 1) * 2], bh[nf >> 1][(nf & 1) * 2 + 1]);
            }
        }
    }
}

// ---------------------------------------------------------------------------
// proj_gemm: grid (64, 6), 256 threads, 2 CTAs/SM. Fused epilogues.
// ---------------------------------------------------------------------------
__global__ __launch_bounds__(256, 2) void proj_gemm(
    const float* __restrict__ bq, const float* __restrict__ bk,
    const float* __restrict__ bv, const float* __restrict__ bg)
{
    extern __shared__ char smraw[];
    __shared__ float sq2[128];
    uint32_t sbase = smem_u32(smraw);
    const int tid = threadIdx.x;
    const int m0 = blockIdx.x * 128;
    const int slab = blockIdx.y;
    const int nbase = slab * 128;

    if (tid < 128) sq2[tid] = 0.0f;

    const __half* A = g_Xh + (size_t)m0 * DD;
    const __half* B = g_Wt + (size_t)nbase * DD;

    const int warp = tid >> 5, lane = tid & 31;
    const int lr = lane & 7, gq = lane >> 3;
    const int wm = (warp & 1) * 64, wn = (warp >> 1) * 32;
    const uint32_t a_off = (wm + lr + (gq & 1) * 8) * 144 + (gq >> 1) * 16;
    const uint32_t b_off = (wn + lr + (gq >> 1) * 8) * 144 + (gq & 1) * 16;

    float acc[4][4][4] = {};

    stage_copy(sbase, A, DD, B, DD, 0, tid);
    CP_COMMIT();
    for (int kb = 0; kb < 16; kb++) {
        if (kb + 1 < 16) {
            stage_copy(sbase + ((kb + 1) & 1) * STAGE_BYTES,
                       A, DD, B, DD, (kb + 1) * 64, tid);
            CP_COMMIT();
            CP_WAIT1();
        } else {
            CP_WAIT0();
        }
        __syncthreads();
        compute_stage(sbase + (kb & 1) * STAGE_BYTES, a_off, b_off, acc);
        __syncthreads();
    }

    const int mrow = lane >> 2, ncol = (lane & 3) * 2;

    if (slab < 2) {
        const float* bias = (slab == 0) ? bq : bk;
        __half* dst = (slab == 0) ? g_Qh : g_Kh;
        float part[4][2] = {};
        #pragma unroll
        for (int mf = 0; mf < 4; mf++) {
            int lm = wm + mf * 16 + mrow;
            #pragma unroll
            for (int nf = 0; nf < 4; nf++) {
                int n = wn + nf * 8 + ncol;
                float b0 = bias[n], b1 = bias[n + 1];
                __half h00 = __float2half_rn(acc[mf][nf][0] + b0);
                __half h01 = __float2half_rn(acc[mf][nf][1] + b1);
                __half h10 = __float2half_rn(acc[mf][nf][2] + b0);
                __half h11 = __float2half_rn(acc[mf][nf][3] + b1);
                __half2 p0(h00, h01), p1(h10, h11);
                *(uint32_t*)&dst[(size_t)(m0 + lm) * DQKC + n] =
                    *reinterpret_cast<uint32_t*>(&p0);
                *(uint32_t*)&dst[(size_t)(m0 + lm + 8) * DQKC + n] =
                    *reinterpret_cast<uint32_t*>(&p1);
                float f00 = __half2float(h00), f01 = __half2float(h01);
                float f10 = __half2float(h10), f11 = __half2float(h11);
                part[mf][0] += f00 * f00 + f01 * f01;
                part[mf][1] += f10 * f10 + f11 * f11;
            }
        }
        #pragma unroll
        for (int mf = 0; mf < 4; mf++) {
            float s0 = part[mf][0], s1 = part[mf][1];
            s0 += __shfl_xor_sync(0xffffffffu, s0, 1);
            s0 += __shfl_xor_sync(0xffffffffu, s0, 2);
            s1 += __shfl_xor_sync(0xffffffffu, s1, 1);
            s1 += __shfl_xor_sync(0xffffffffu, s1, 2);
            if ((lane & 3) == 0) {
                int lm = wm + mf * 16 + mrow;
                atomicAdd(&sq2[lm], s0);
                atomicAdd(&sq2[lm + 8], s1);
            }
        }
        __syncthreads();
        if (tid < 128) {
            if (slab == 0) g_Q2[m0 + tid] = sq2[tid];
            else           g_K2[m0 + tid] = sq2[tid];
        }
    } else if (slab < 4) {
        __half* Vs = (__half*)smraw;
        const int VSP = 130;
        #pragma unroll
        for (int mf = 0; mf < 4; mf++) {
            int lm = wm + mf * 16 + mrow;
            #pragma unroll
            for (int nf = 0; nf < 4; nf++) {
                int n = wn + nf * 8 + ncol;
                float b0 = bv[((slab == 3) ? 128 : 0) + n];
                float b1 = bv[((slab == 3) ? 128 : 0) + n + 1];
                *(uint32_t*)&Vs[lm * VSP + n] =
                    pack2h(acc[mf][nf][0] + b0, acc[mf][nf][1] + b1);
                *(uint32_t*)&Vs[(lm + 8) * VSP + n] =
                    pack2h(acc[mf][nf][2] + b0, acc[mf][nf][3] + b1);
            }
        }
        __syncthreads();
        const int batch = m0 >> 11;
        const int mloc  = m0 & 2047;
        const int nbo   = (slab == 3) ? 128 : 0;
        #pragma unroll
        for (int i = 0; i < 8; i++) {
            int idx = tid + i * 256;
            int n = idx >> 4;
            int mseg = idx & 15;
            __half tmp[8];
            #pragma unroll
            for (int j = 0; j < 8; j++)
                tmp[j] = Vs[(mseg * 8 + j) * VSP + n];
            *(uint4*)&g_Vt[((size_t)batch * DVC + nbo + n) * SS + mloc + mseg * 8] =
                *(uint4*)tmp;
        }
    } else {
        const int nbo = (slab == 5) ? 128 : 0;
        #pragma unroll
        for (int mf = 0; mf < 4; mf++) {
            int m = m0 + wm + mf * 16 + mrow;
            #pragma unroll
            for (int nf = 0; nf < 4; nf++) {
                int n = wn + nf * 8 + ncol;
                float b0 = bg[nbo + n], b1 = bg[nbo + n + 1];
                *(uint32_t*)&g_Gh[(size_t)m * DVC + nbo + n] =
                    pack2h(acc[mf][nf][0] + b0, acc[mf][nf][1] + b1);
                *(uint32_t*)&g_Gh[(size_t)(m + 8) * DVC + nbo + n] =
                    pack2h(acc[mf][nf][2] + b0, acc[mf][nf][3] + b1);
            }
        }
    }
}

// ---------------------------------------------------------------------------
// attn: single-sync pipelined Shepard attention.
// Triple-buffered K/V/k2, double-buffered w. One __syncthreads per chunk.
// Iteration i: sync; prefetch(i+2); B(i); A(i+1); w(i+1).
// ---------------------------------------------------------------------------
#define QPITCH 272
#define KPITCH 272
#define VPITCH 144
#define WPITCH 144

#define KBUF_BYTES 17408
#define VBUF_BYTES 36864
#define WBUF_BYTES 9216

#define OFF_QH  0
#define OFF_KH  17408
#define OFF_VH  69632
#define OFF_WH  180224
#define OFF_Q2  198656
#define OFF_K2  198912
#define OFF_WS  199680
#define ATT_SMEM_BYTES 199936

#define WSCALE 1024.0f

__device__ __forceinline__ void attn_load_k(uint32_t sKh, int krow0c, int tid)
{
    #pragma unroll
    for (int i = 0; i < 4; i++) {
        int idx = tid + i * 256;
        int row = idx >> 4, seg = idx & 15;
        CPA16(sKh + row * KPITCH + seg * 16,
              g_Kh + (size_t)(krow0c + row) * DQKC + seg * 8);
    }
}

__device__ __forceinline__ void attn_load_v(uint32_t sVh, int b, int kb, int tid)
{
    #pragma unroll
    for (int i = 0; i < 8; i++) {
        int idx = tid + i * 256;
        int n = idx >> 3, seg = idx & 7;
        CPA16(sVh + n * VPITCH + seg * 16,
              g_Vt + ((size_t)b * DVC + n) * (size_t)SS + kb * 64 + seg * 8);
    }
}

// Phase A: S = Q @ K^T (64x64, K=128) for one chunk
__device__ __forceinline__ void phase_a(
    uint32_t sb, uint32_t sKH, uint32_t aQ, uint32_t bK, int wmA,
    float s[2][2][4])
{
    #pragma unroll
    for (int i = 0; i < 2; i++)
        #pragma unroll
        for (int j = 0; j < 2; j++)
            #pragma unroll
            for (int k = 0; k < 4; k++) s[i][j][k] = 0.0f;
    #pragma unroll
    for (int ks = 0; ks < 8; ks++) {
        uint32_t ah[2][4], bh[4];
        LDSM4(ah[0], sb + OFF_QH + aQ + (wmA +  0) * QPITCH + ks * 32);
        LDSM4(ah[1], sb + OFF_QH + aQ + (wmA + 16) * QPITCH + ks * 32);
        LDSM4(bh, sKH + bK + ks * 32);
        #pragma unroll
        for (int mf = 0; mf < 2; mf++) {
            #pragma unroll
            for (int nf = 0; nf < 2; nf++)
                MMA16816(s[mf][nf], ah[mf], bh[nf * 2], bh[nf * 2 + 1]);
        }
    }
}

// Phase W: w = WSCALE/max(d2,eps) -> fp16 in wbuf; quad-reduced wsum atomics
__device__ __forceinline__ void phase_w(
    char* smc, uint32_t wOff, const float* k2s, const float* q2s, float* wsum,
    float s[2][2][4], int wmA, int wnA, int mrow, int ncol, int lane)
{
    #pragma unroll
    for (int mf = 0; mf < 2; mf++) {
        int r0 = wmA + mf * 16 + mrow;
        int r1 = r0 + 8;
        float q20 = q2s[r0], q21 = q2s[r1];
        float rs0 = 0.0f, rs1 = 0.0f;
        #pragma unroll
        for (int nf = 0; nf < 2; nf++) {
            int n0 = wnA + nf * 8 + ncol;
            float k20 = k2s[n0], k21 = k2s[n0 + 1];
            float d00 = fmaxf(q20 + k20 - 2.0f * s[mf][nf][0], 0.0f);
            float d01 = fmaxf(q20 + k21 - 2.0f * s[mf][nf][1], 0.0f);
            float d10 = fmaxf(q21 + k20 - 2.0f * s[mf][nf][2], 0.0f);
            float d11 = fmaxf(q21 + k21 - 2.0f * s[mf][nf][3], 0.0f);
            __half h00 = __float2half_rn(__fdividef(WSCALE, fmaxf(d00, 1e-16f)));
            __half h01 = __float2half_rn(__fdividef(WSCALE, fmaxf(d01, 1e-16f)));
            __half h10 = __float2half_rn(__fdividef(WSCALE, fmaxf(d10, 1e-16f)));
            __half h11 = __float2half_rn(__fdividef(WSCALE, fmaxf(d11, 1e-16f)));
            __half2 p0(h00, h01), p1(h10, h11);
            *(uint32_t*)(smc + wOff + r0 * WPITCH + n0 * 2) =
                *reinterpret_cast<uint32_t*>(&p0);
            *(uint32_t*)(smc + wOff + r1 * WPITCH + n0 * 2) =
                *reinterpret_cast<uint32_t*>(&p1);
            rs0 += __half2float(h00) + __half2float(h01);
            rs1 += __half2float(h10) + __half2float(h11);
        }
        rs0 += __shfl_xor_sync(0xffffffffu, rs0, 1);
        rs0 += __shfl_xor_sync(0xffffffffu, rs0, 2);
        rs1 += __shfl_xor_sync(0xffffffffu, rs1, 1);
        rs1 += __shfl_xor_sync(0xffffffffu, rs1, 2);
        if ((lane & 3) == 0) {
            atomicAdd(&wsum[r0], rs0);
            atomicAdd(&wsum[r1], rs1);
        }
    }
}

__global__ __launch_bounds__(256) void attn_kernel()
{
    extern __shared__ char smc[];
    const uint32_t sb = smem_u32(smc);
    float* q2s  = (float*)(smc + OFF_Q2);
    float* wsum = (float*)(smc + OFF_WS);

    const int tid  = threadIdx.x;
    const int warp = tid >> 5, lane = tid & 31;
    const int lr = lane & 7, gq = lane >> 3;
    const int mrow = lane >> 2, ncol = (lane & 3) * 2;

    const int b  = blockIdx.x >> 5;
    const int qt = blockIdx.x & 31;
    const int qrow0 = b * SS + qt * 64;
    const int krow0 = b * SS;

    // Prologue: Q + chunk 0 (group 0), chunk 1 (group 1)
    #pragma unroll
    for (int i = 0; i < 4; i++) {
        int idx = tid + i * 256;
        int row = idx >> 4, seg = idx & 15;
        CPA16(sb + OFF_QH + row * QPITCH + seg * 16,
              g_Qh + (size_t)(qrow0 + row) * DQKC + seg * 8);
    }
    attn_load_k(sb + OFF_KH, krow0, tid);
    attn_load_v(sb + OFF_VH, b, 0, tid);
    if (tid < 16) CPA16(sb + OFF_K2 + tid * 16, g_K2 + krow0 + tid * 4);
    CP_COMMIT();
    attn_load_k(sb + OFF_KH + KBUF_BYTES, krow0 + 64, tid);
    attn_load_v(sb + OFF_VH + VBUF_BYTES, b, 1, tid);
    if (tid < 16) CPA16(sb + OFF_K2 + 256 + tid * 16, g_K2 + krow0 + 64 + tid * 4);
    CP_COMMIT();
    if (tid < 64) { wsum[tid] = 0.0f; q2s[tid] = g_Q2[qrow0 + tid]; }

    float acc[4][4][4] = {};

    const int wmA = (warp & 1) * 32;
    const int wnA = (warp >> 1) * 16;
    const int wnB = warp * 32;
    const uint32_t aQ = (lr + (gq & 1) * 8) * QPITCH + (gq >> 1) * 16;
    const uint32_t bK = (wnA + lr + (gq >> 1) * 8) * KPITCH + (gq & 1) * 16;
    const uint32_t aW = (lr + (gq & 1) * 8) * WPITCH + (gq >> 1) * 16;
    const uint32_t bV = (wnB + lr + (gq >> 1) * 8) * VPITCH + (gq & 1) * 16;

    // A(0) + w(0) after chunk 0 arrives
    CP_WAIT1();
    __syncthreads();
    {
        float s[2][2][4];
        phase_a(sb, sb + OFF_KH, aQ, bK, wmA, s);
        phase_w(smc, OFF_WH, (const float*)(smc + OFF_K2), q2s, wsum,
                s, wmA, wnA, mrow, ncol, lane);
    }

    for (int kc = 0; kc < 32; kc++) {
        CP_WAIT0();
        __syncthreads();   // w(kc) visible; chunk kc+1 visible; B(kc-1) reads done

        // prefetch chunk kc+2 (buffer ((kc+2)%3) last read pre-sync)
        if (kc + 2 < 32) {
            int j = (kc + 2) % 3;
            attn_load_k(sb + OFF_KH + j * KBUF_BYTES, krow0 + (kc + 2) * 64, tid);
            attn_load_v(sb + OFF_VH + j * VBUF_BYTES, b, kc + 2, tid);
            if (tid < 16) CPA16(sb + OFF_K2 + j * 256 + tid * 16,
                                g_K2 + krow0 + (kc + 2) * 64 + tid * 4);
            CP_COMMIT();
        }

        // ---- Phase B(kc): acc += w @ V ----
        {
            const uint32_t sVH = sb + OFF_VH + (kc % 3) * VBUF_BYTES;
            const uint32_t wOff = sb + OFF_WH + (kc & 1) * WBUF_BYTES;
            #pragma unroll
            for (int ks = 0; ks < 4; ks++) {
                uint32_t awh[4][4], bvh[2][4];
                #pragma unroll
                for (int mf = 0; mf < 4; mf++)
                    LDSM4(awh[mf], wOff + aW + mf * 16 * WPITCH + ks * 32);
                #pragma unroll
                for (int np = 0; np < 2; np++)
                    LDSM4(bvh[np], sVH + bV + np * 16 * VPITCH + ks * 32);
                #pragma unroll
                for (int mf = 0; mf < 4; mf++) {
                    #pragma unroll
                    for (int nf = 0; nf < 4; nf++) {
                        MMA16816(acc[mf][nf], awh[mf],
                                 bvh[nf >> 1][(nf & 1) * 2],
                                 bvh[nf >> 1][(nf & 1) * 2 + 1]);
                    }
                }
            }
        }

        // ---- A(kc+1) + w(kc+1) ----
        if (kc + 1 < 32) {
            int j = (kc + 1) % 3;
            float s[2][2][4];
            phase_a(sb, sb + OFF_KH + j * KBUF_BYTES, aQ, bK, wmA, s);
            phase_w(smc, OFF_WH + ((kc + 1) & 1) * WBUF_BYTES,
                    (const float*)(smc + OFF_K2 + j * 256), q2s, wsum,
                    s, wmA, wnA, mrow, ncol, lane);
        }
    }

    // ---- Epilogue: normalize, gate with fp16 G, pack P ----
    #pragma unroll
    for (int mf = 0; mf < 4; mf++) {
        int lm0 = mf * 16 + mrow;
        float inv0 = 1.0f / wsum[lm0];
        float inv1 = 1.0f / wsum[lm0 + 8];
        size_t gm0 = (size_t)(qrow0 + lm0) * DVC;
        size_t gm1 = gm0 + 8 * DVC;
        #pragma unroll
        for (int nf = 0; nf < 4; nf++) {
            int n = wnB + nf * 8 + ncol;
            float2 gA = __half22float2(*(const __half2*)&g_Gh[gm0 + n]);
            float2 gB = __half22float2(*(const __half2*)&g_Gh[gm1 + n]);
            *(uint32_t*)&g_Ph[gm0 + n] =
                pack2h(acc[mf][nf][0] * inv0 * gA.x, acc[mf][nf][1] * inv0 * gA.y);
            *(uint32_t*)&g_Ph[gm1 + n] =
                pack2h(acc[mf][nf][2] * inv1 * gB.x, acc[mf][nf][3] * inv1 * gB.y);
        }
    }
}

// ---------------------------------------------------------------------------
// out_gemm: out = X + P @ Wp + bp   (BK=64, 4 k-blocks), 2 CTAs/SM
// ---------------------------------------------------------------------------
__global__ __launch_bounds__(256, 2) void out_gemm(
    const float* __restrict__ X, const float* __restrict__ bp,
    float* __restrict__ outp)
{
    extern __shared__ char smraw[];
    uint32_t sbase = smem_u32(smraw);
    const int tid = threadIdx.x;
    const int m0 = blockIdx.x * 128;
    const int n0 = blockIdx.y * 128;

    const __half* A = g_Ph + (size_t)m0 * DVC;
    const __half* B = g_Wpt + (size_t)n0 * DVC;

    const int warp = tid >> 5, lane = tid & 31;
    const int lr = lane & 7, gq = lane >> 3;
    const int wm = (warp & 1) * 64, wn = (warp >> 1) * 32;
    const uint32_t a_off = (wm + lr + (gq & 1) * 8) * 144 + (gq >> 1) * 16;
    const uint32_t b_off = (wn + lr + (gq >> 1) * 8) * 144 + (gq & 1) * 16;

    float acc[4][4][4] = {};

    stage_copy(sbase, A, DVC, B, DVC, 0, tid);
    CP_COMMIT();
    for (int kb = 0; kb < 4; kb++) {
        if (kb + 1 < 4) {
            stage_copy(sbase + ((kb + 1) & 1) * STAGE_BYTES,
                       A, DVC, B, DVC, (kb + 1) * 64, tid);
            CP_COMMIT();
            CP_WAIT1();
        } else {
            CP_WAIT0();
        }
        __syncthreads();
        compute_stage(sbase + (kb & 1) * STAGE_BYTES, a_off, b_off, acc);
        __syncthreads();
    }

    const int mrow = lane >> 2, ncol = (lane & 3) * 2;
    #pragma unroll
    for (int mf = 0; mf < 4; mf++) {
        #pragma unroll
        for (int nf = 0; nf < 4; nf++) {
            int m = m0 + wm + mf * 16 + mrow;
            int n = n0 + wn + nf * 8 + ncol;
            float b0 = bp[n], b1 = bp[n + 1];
            float2 x0 = *(const float2*)&X[(size_t)m * DD + n];
            float2 x1 = *(const float2*)&X[(size_t)(m + 8) * DD + n];
            *(float2*)&outp[(size_t)m * DD + n] =
                make_float2(acc[mf][nf][0] + b0 + x0.x, acc[mf][nf][1] + b1 + x0.y);
            *(float2*)&outp[(size_t)(m + 8) * DD + n] =
                make_float2(acc[mf][nf][2] + b0 + x1.x, acc[mf][nf][3] + b1 + x1.y);
        }
    }
}

// ---------------------------------------------------------------------------
extern "C" void kernel_launch(void* const* d_in, const int* in_sizes, int n_in,
                              void* d_out, int out_size)
{
    const float* X  = (const float*)d_in[0];
    const float* Wq = (const float*)d_in[1];
    const float* bq = (const float*)d_in[2];
    const float* Wk = (const float*)d_in[3];
    const float* bk = (const float*)d_in[4];
    const float* Wv = (const float*)d_in[5];
    const float* bv = (const float*)d_in[6];
    const float* Wg = (const float*)d_in[7];
    const float* bg = (const float*)d_in[8];
    const float* Wp = (const float*)d_in[9];
    const float* bp = (const float*)d_in[10];
    float* out = (float*)d_out;

    cudaFuncSetAttribute(proj_gemm, cudaFuncAttributeMaxDynamicSharedMemorySize, GEMM_SMEM_BYTES);
    cudaFuncSetAttribute(out_gemm,  cudaFuncAttributeMaxDynamicSharedMemorySize, GEMM_SMEM_BYTES);
    cudaFuncSetAttribute(attn_kernel, cudaFuncAttributeMaxDynamicSharedMemorySize, ATT_SMEM_BYTES);

    split_x_kernel<<<MM * DD / 1024, 256>>>(X);
    split_w_kernel<<<(NPROJ * DD + DD * DVC) / 256, 256>>>(Wq, Wk, Wv, Wg, Wp);
    proj_gemm<<<dim3(64, 6), 256, GEMM_SMEM_BYTES>>>(bq, bk, bv, bg);
    attn_kernel<<<128, 256, ATT_SMEM_BYTES>>>();
    out_gemm<<<dim3(64, 8), 256, GEMM_SMEM_BYTES>>>(X, bp, out);
}